// round 1
// baseline (speedup 1.0000x reference)
#include <cuda_runtime.h>

// Problem constants (fixed by setup_inputs)
#define BB    8
#define N1    8192
#define M2    2048
#define C1    128
#define C2    256
#define CIN   384
#define H0    256
#define H1    128
#define NPTS  (BB * N1)   // 65536

// ---------------- scratch (device globals; no allocations allowed) ----------
__device__ float g_feat[(size_t)NPTS * CIN];   // ~100 MB
__device__ float g_h1[(size_t)NPTS * H0];      // ~67 MB
__device__ float g_scale0[BB * H0];
__device__ float g_shift0[BB * H0];
__device__ float g_scale1[BB * H1];
__device__ float g_shift1[BB * H1];

typedef unsigned long long u64;

__device__ __forceinline__ u64 f2fma(u64 a, u64 b, u64 c) {
    u64 d;
    asm("fma.rn.f32x2 %0, %1, %2, %3;" : "=l"(d) : "l"(a), "l"(b), "l"(c));
    return d;
}
__device__ __forceinline__ u64 f2pack(float x, float y) {
    u64 d;
    asm("mov.b64 %0, {%1, %2};" : "=l"(d) : "f"(x), "f"(y));
    return d;
}
__device__ __forceinline__ float4 ldg4(const float* p) { return *(const float4*)p; }

// ---------------- kernel 1: 3-NN + interpolate + concat ---------------------
__global__ __launch_bounds__(256) void knn_interp_kernel(
    const float* __restrict__ xyz1, const float* __restrict__ xyz2,
    const float* __restrict__ points1, const float* __restrict__ points2)
{
    __shared__ float sx[M2], sy[M2], sz[M2], sq[M2];
    const int b = blockIdx.y;
    const float* x2 = xyz2 + (size_t)b * M2 * 3;
    for (int j = threadIdx.x; j < M2; j += 256) {
        float x = x2[j * 3 + 0], y = x2[j * 3 + 1], z = x2[j * 3 + 2];
        sx[j] = x; sy[j] = y; sz[j] = z;
        sq[j] = x * x + y * y + z * z;
    }
    __syncthreads();

    const int n = blockIdx.x * 256 + threadIdx.x;
    const float* p1 = xyz1 + ((size_t)b * N1 + n) * 3;
    const float px = p1[0], py = p1[1], pz = p1[2];
    const float psq = px * px + py * py + pz * pz;

    float d0 = 1e30f, d1 = 1e30f, d2 = 1e30f;
    int i0 = 0, i1 = 0, i2 = 0;
#pragma unroll 4
    for (int j = 0; j < M2; ++j) {
        float t = fmaf(px, sx[j], fmaf(py, sy[j], pz * sz[j]));
        float d = psq + sq[j] - 2.0f * t;   // same formula as reference
        if (d < d2) {
            if (d < d1) {
                if (d < d0) { d2 = d1; i2 = i1; d1 = d0; i1 = i0; d0 = d; i0 = j; }
                else        { d2 = d1; i2 = i1; d1 = d;  i1 = j; }
            } else          { d2 = d;  i2 = j; }
        }
    }
    float w0 = 1.0f / (d0 + 1e-8f);
    float w1 = 1.0f / (d1 + 1e-8f);
    float w2 = 1.0f / (d2 + 1e-8f);
    const float inv = 1.0f / (w0 + w1 + w2);
    w0 *= inv; w1 *= inv; w2 *= inv;

    const size_t m = (size_t)b * N1 + n;
    float* fo = g_feat + m * CIN;
    const float* pp1 = points1 + m * C1;
#pragma unroll 8
    for (int c = 0; c < C1; c += 4)
        *(float4*)(fo + c) = *(const float4*)(pp1 + c);

    const float* r0 = points2 + ((size_t)b * M2 + i0) * C2;
    const float* r1 = points2 + ((size_t)b * M2 + i1) * C2;
    const float* r2 = points2 + ((size_t)b * M2 + i2) * C2;
#pragma unroll 8
    for (int c = 0; c < C2; c += 4) {
        float4 a = *(const float4*)(r0 + c);
        float4 bvec = *(const float4*)(r1 + c);
        float4 cvec = *(const float4*)(r2 + c);
        float4 o;
        o.x = w0 * a.x + w1 * bvec.x + w2 * cvec.x;
        o.y = w0 * a.y + w1 * bvec.y + w2 * cvec.y;
        o.z = w0 * a.z + w1 * bvec.z + w2 * cvec.z;
        o.w = w0 * a.w + w1 * bvec.w + w2 * cvec.w;
        *(float4*)(fo + C1 + c) = o;
    }
}

// ---------------- SGEMM: C[m,n] = sum_k A'[m,k] * W[n,k] --------------------
// A' = A (useNorm==0)  or  relu(A*scale[k]+shift[k]) (useNorm==1, per-batch)
// BM=BN=128, BK=16, 256 threads, 8x8 per thread, fma.rn.f32x2 inner loop.
__global__ __launch_bounds__(256) void sgemm_kernel(
    const float* __restrict__ A, const float* __restrict__ W, float* __restrict__ C,
    int K, int Nn,
    const float* __restrict__ scale, const float* __restrict__ shift, int useNorm)
{
    __shared__ float As[16][128];
    __shared__ float Bs[16][128];
    __shared__ float sSc[256], sSh[256];

    const int t = threadIdx.x;
    const int row0 = blockIdx.x * 128;
    const int col0 = blockIdx.y * 128;
    const int b = row0 >> 13;             // 8192 rows per batch, 128 | 8192

    if (useNorm) {
        for (int i = t; i < K; i += 256) {
            sSc[i] = scale[b * K + i];
            sSh[i] = shift[b * K + i];
        }
    }
    __syncthreads();

    const int r   = t >> 2;
    const int kkb = (t & 3) * 4;
    const float* Abase = A + (size_t)(row0 + r) * K + kkb;
    const float* Wbase = W + (size_t)(col0 + r) * K + kkb;

    u64 acc[8][4];
#pragma unroll
    for (int i = 0; i < 8; ++i)
#pragma unroll
        for (int j = 0; j < 4; ++j) acc[i][j] = 0ull;

    const int trow = t >> 4;
    const int tcol = t & 15;
    const int ntiles = K >> 4;

    float4 a0, a1, w0v, w1v;
    {   // prefetch tile 0
        a0 = ldg4(Abase);
        a1 = ldg4(Abase + (size_t)64 * K);
        w0v = ldg4(Wbase);
        w1v = ldg4(Wbase + (size_t)64 * K);
        if (useNorm) {
            const int k = kkb;
            a0.x = fmaxf(0.f, fmaf(a0.x, sSc[k + 0], sSh[k + 0]));
            a0.y = fmaxf(0.f, fmaf(a0.y, sSc[k + 1], sSh[k + 1]));
            a0.z = fmaxf(0.f, fmaf(a0.z, sSc[k + 2], sSh[k + 2]));
            a0.w = fmaxf(0.f, fmaf(a0.w, sSc[k + 3], sSh[k + 3]));
            a1.x = fmaxf(0.f, fmaf(a1.x, sSc[k + 0], sSh[k + 0]));
            a1.y = fmaxf(0.f, fmaf(a1.y, sSc[k + 1], sSh[k + 1]));
            a1.z = fmaxf(0.f, fmaf(a1.z, sSc[k + 2], sSh[k + 2]));
            a1.w = fmaxf(0.f, fmaf(a1.w, sSc[k + 3], sSh[k + 3]));
        }
    }

    for (int kt = 0; kt < ntiles; ++kt) {
        As[kkb + 0][r] = a0.x; As[kkb + 1][r] = a0.y;
        As[kkb + 2][r] = a0.z; As[kkb + 3][r] = a0.w;
        As[kkb + 0][r + 64] = a1.x; As[kkb + 1][r + 64] = a1.y;
        As[kkb + 2][r + 64] = a1.z; As[kkb + 3][r + 64] = a1.w;
        Bs[kkb + 0][r] = w0v.x; Bs[kkb + 1][r] = w0v.y;
        Bs[kkb + 2][r] = w0v.z; Bs[kkb + 3][r] = w0v.w;
        Bs[kkb + 0][r + 64] = w1v.x; Bs[kkb + 1][r + 64] = w1v.y;
        Bs[kkb + 2][r + 64] = w1v.z; Bs[kkb + 3][r + 64] = w1v.w;
        __syncthreads();

        if (kt + 1 < ntiles) {
            const int k0 = (kt + 1) * 16;
            a0 = ldg4(Abase + k0);
            a1 = ldg4(Abase + (size_t)64 * K + k0);
            w0v = ldg4(Wbase + k0);
            w1v = ldg4(Wbase + (size_t)64 * K + k0);
            if (useNorm) {
                const int k = k0 + kkb;
                a0.x = fmaxf(0.f, fmaf(a0.x, sSc[k + 0], sSh[k + 0]));
                a0.y = fmaxf(0.f, fmaf(a0.y, sSc[k + 1], sSh[k + 1]));
                a0.z = fmaxf(0.f, fmaf(a0.z, sSc[k + 2], sSh[k + 2]));
                a0.w = fmaxf(0.f, fmaf(a0.w, sSc[k + 3], sSh[k + 3]));
                a1.x = fmaxf(0.f, fmaf(a1.x, sSc[k + 0], sSh[k + 0]));
                a1.y = fmaxf(0.f, fmaf(a1.y, sSc[k + 1], sSh[k + 1]));
                a1.z = fmaxf(0.f, fmaf(a1.z, sSc[k + 2], sSh[k + 2]));
                a1.w = fmaxf(0.f, fmaf(a1.w, sSc[k + 3], sSh[k + 3]));
            }
        }

#pragma unroll
        for (int kk = 0; kk < 16; ++kk) {
            float4 fa0 = *(const float4*)&As[kk][trow * 8];
            float4 fa1 = *(const float4*)&As[kk][trow * 8 + 4];
            const u64* bp = (const u64*)&Bs[kk][tcol * 8];
            u64 b0 = bp[0], b1 = bp[1], b2 = bp[2], b3 = bp[3];
            float av[8] = {fa0.x, fa0.y, fa0.z, fa0.w, fa1.x, fa1.y, fa1.z, fa1.w};
#pragma unroll
            for (int i = 0; i < 8; ++i) {
                u64 ap = f2pack(av[i], av[i]);
                acc[i][0] = f2fma(ap, b0, acc[i][0]);
                acc[i][1] = f2fma(ap, b1, acc[i][1]);
                acc[i][2] = f2fma(ap, b2, acc[i][2]);
                acc[i][3] = f2fma(ap, b3, acc[i][3]);
            }
        }
        __syncthreads();
    }

#pragma unroll
    for (int i = 0; i < 8; ++i) {
        float* cp = C + (size_t)(row0 + trow * 8 + i) * Nn + col0 + tcol * 8;
        ulonglong2 v0; v0.x = acc[i][0]; v0.y = acc[i][1];
        ulonglong2 v1; v1.x = acc[i][2]; v1.y = acc[i][3];
        *(ulonglong2*)cp = v0;
        *(ulonglong2*)(cp + 4) = v1;
    }
}

// ---------------- GN stats: per (batch, group) mean/var -> scale/shift ------
__global__ __launch_bounds__(256) void gn_stats_kernel(
    const float* __restrict__ X, int C, int CPG,
    const float* __restrict__ gw, const float* __restrict__ gb,
    float* __restrict__ scale, float* __restrict__ shift)
{
    const int g = blockIdx.x, b = blockIdx.y;
    const float* base = X + (size_t)b * N1 * C + g * CPG;
    float s = 0.f, ss = 0.f;
    for (int n = threadIdx.x; n < N1; n += 256) {
        const float* p = base + (size_t)n * C;
        for (int c = 0; c < CPG; c += 4) {
            float4 v = *(const float4*)(p + c);
            s  += v.x + v.y + v.z + v.w;
            ss += v.x * v.x + v.y * v.y + v.z * v.z + v.w * v.w;
        }
    }
    __shared__ float rs[32], rss[32];
#pragma unroll
    for (int o = 16; o; o >>= 1) {
        s  += __shfl_down_sync(~0u, s, o);
        ss += __shfl_down_sync(~0u, ss, o);
    }
    const int w = threadIdx.x >> 5, l = threadIdx.x & 31;
    if (l == 0) { rs[w] = s; rss[w] = ss; }
    __syncthreads();
    if (w == 0) {
        s  = (l < 8) ? rs[l]  : 0.f;
        ss = (l < 8) ? rss[l] : 0.f;
#pragma unroll
        for (int o = 4; o; o >>= 1) {
            s  += __shfl_down_sync(~0u, s, o);
            ss += __shfl_down_sync(~0u, ss, o);
        }
        if (l == 0) { rs[0] = s; rss[0] = ss; }
    }
    __syncthreads();
    if (threadIdx.x < CPG) {
        const float cnt = (float)N1 * (float)CPG;
        const float mean = rs[0] / cnt;
        const float var  = rss[0] / cnt - mean * mean;
        const float rstd = rsqrtf(var + 1e-5f);
        const int c = g * CPG + threadIdx.x;
        const float sc = rstd * gw[c];
        scale[b * C + c] = sc;
        shift[b * C + c] = gb[c] - mean * sc;
    }
}

// ---------------- final GN1 + ReLU in-place on d_out ------------------------
__global__ __launch_bounds__(256) void apply_kernel(
    float* __restrict__ out,
    const float* __restrict__ scale, const float* __restrict__ shift)
{
    const size_t i = ((size_t)blockIdx.x * 256 + threadIdx.x) * 4;
    const int c = (int)(i & (H1 - 1));
    const int b = (int)(i >> 20);         // i / (8192*128)
    const int idx = b * H1 + c;
    float4 v = *(float4*)(out + i);
    v.x = fmaxf(0.f, fmaf(v.x, scale[idx + 0], shift[idx + 0]));
    v.y = fmaxf(0.f, fmaf(v.y, scale[idx + 1], shift[idx + 1]));
    v.z = fmaxf(0.f, fmaf(v.z, scale[idx + 2], shift[idx + 2]));
    v.w = fmaxf(0.f, fmaf(v.w, scale[idx + 3], shift[idx + 3]));
    *(float4*)(out + i) = v;
}

// ---------------- launcher ---------------------------------------------------
extern "C" void kernel_launch(void* const* d_in, const int* in_sizes, int n_in,
                              void* d_out, int out_size)
{
    const float* xyz1    = (const float*)d_in[0];
    const float* xyz2    = (const float*)d_in[1];
    const float* points1 = (const float*)d_in[2];
    const float* points2 = (const float*)d_in[3];
    const float* w0      = (const float*)d_in[4];
    const float* w1      = (const float*)d_in[5];
    const float* gn0w    = (const float*)d_in[6];
    const float* gn0b    = (const float*)d_in[7];
    const float* gn1w    = (const float*)d_in[8];
    const float* gn1b    = (const float*)d_in[9];
    float* out = (float*)d_out;

    float *feat, *h1, *sc0, *sh0, *sc1, *sh1;
    cudaGetSymbolAddress((void**)&feat, g_feat);
    cudaGetSymbolAddress((void**)&h1,   g_h1);
    cudaGetSymbolAddress((void**)&sc0,  g_scale0);
    cudaGetSymbolAddress((void**)&sh0,  g_shift0);
    cudaGetSymbolAddress((void**)&sc1,  g_scale1);
    cudaGetSymbolAddress((void**)&sh1,  g_shift1);

    // 1) 3-NN interpolate + concat -> g_feat (65536 x 384)
    knn_interp_kernel<<<dim3(N1 / 256, BB), 256>>>(xyz1, xyz2, points1, points2);

    // 2) h1 = feat @ w0^T  (65536 x 384) x (256 x 384)^T -> (65536 x 256)
    sgemm_kernel<<<dim3(NPTS / 128, H0 / 128), 256>>>(feat, w0, h1, CIN, H0,
                                                      nullptr, nullptr, 0);

    // 3) GN0 stats -> folded scale/shift per (b, channel)
    gn_stats_kernel<<<dim3(32, BB), 256>>>(h1, H0, H0 / 32, gn0w, gn0b, sc0, sh0);

    // 4) out = relu(gn0(h1)) @ w1^T -> (65536 x 128), GN0+ReLU fused at A-load
    sgemm_kernel<<<dim3(NPTS / 128, H1 / 128), 256>>>(h1, w1, out, H0, H1,
                                                      sc0, sh0, 1);

    // 5) GN1 stats on out
    gn_stats_kernel<<<dim3(32, BB), 256>>>(out, H1, H1 / 32, gn1w, gn1b, sc1, sh1);

    // 6) GN1 + ReLU in-place
    apply_kernel<<<(NPTS * H1) / (256 * 4), 256>>>(out, sc1, sh1);
}

// round 3
// speedup vs baseline: 1.9738x; 1.9738x over previous
#include <cuda_runtime.h>
#include <cuda_bf16.h>
#include <cstdint>
#include <cstddef>

// Problem constants (fixed by setup_inputs)
#define BB    8
#define N1    8192
#define M2    2048
#define C1    128
#define C2    256
#define CIN   384
#define H0    256
#define H1    128
#define NPTS  (BB * N1)   // 65536

// ---------------- scratch (device globals; no allocations allowed) ----------
__device__ __align__(16) __nv_bfloat16 g_fh[(size_t)NPTS * CIN];   // feat hi plane
__device__ __align__(16) __nv_bfloat16 g_fl[(size_t)NPTS * CIN];   // feat lo plane
__device__ __align__(16) __nv_bfloat16 g_w0h[H0 * CIN];
__device__ __align__(16) __nv_bfloat16 g_w0l[H0 * CIN];
__device__ __align__(16) __nv_bfloat16 g_w1h[H1 * H0];
__device__ __align__(16) __nv_bfloat16 g_w1l[H1 * H0];
__device__ float g_h1[(size_t)NPTS * H0];      // ~67 MB
__device__ float g_scale0[BB * H0];
__device__ float g_shift0[BB * H0];
__device__ float g_scale1[BB * H1];
__device__ float g_shift1[BB * H1];

// ---------------- PTX helpers ------------------------------------------------
__device__ __forceinline__ uint32_t smem_u32(const void* p) {
    uint32_t a;
    asm("{ .reg .u64 t; cvta.to.shared.u64 t, %1; cvt.u32.u64 %0, t; }"
        : "=r"(a) : "l"(p));
    return a;
}
__device__ __forceinline__ void cpa16(uint32_t dst, const void* src) {
    asm volatile("cp.async.cg.shared.global [%0], [%1], 16;"
                 :: "r"(dst), "l"(src) : "memory");
}
#define CP_COMMIT() asm volatile("cp.async.commit_group;" ::: "memory")
#define CP_WAIT(n)  asm volatile("cp.async.wait_group %0;" :: "n"(n) : "memory")

__device__ __forceinline__ void ldsm4(uint32_t& r0, uint32_t& r1,
                                      uint32_t& r2, uint32_t& r3, uint32_t a) {
    asm volatile("ldmatrix.sync.aligned.m8n8.x4.shared.b16 {%0,%1,%2,%3}, [%4];"
                 : "=r"(r0), "=r"(r1), "=r"(r2), "=r"(r3) : "r"(a));
}
__device__ __forceinline__ void mma16816(float* c, const uint32_t* a,
                                         uint32_t b0, uint32_t b1) {
    asm volatile(
        "mma.sync.aligned.m16n8k16.row.col.f32.bf16.bf16.f32 "
        "{%0,%1,%2,%3}, {%4,%5,%6,%7}, {%8,%9}, {%0,%1,%2,%3};"
        : "+f"(c[0]), "+f"(c[1]), "+f"(c[2]), "+f"(c[3])
        : "r"(a[0]), "r"(a[1]), "r"(a[2]), "r"(a[3]), "r"(b0), "r"(b1));
}
__device__ __forceinline__ uint32_t bf2bits(__nv_bfloat162 v) {
    return *reinterpret_cast<uint32_t*>(&v);
}

// ---------------- bf16 split-2 GEMM on mma.sync ------------------------------
// C[m,n] = sum_k A'[m,k] * W[n,k]
// USENORM==0: A given as pre-split bf16 planes (Ah, Al); cp.async path.
// USENORM==1: A given fp32 (Af); relu(A*scale+shift) folded at load, split in regs.
// Block 128 x NOUT, 256 threads (8 warps: 2 in M x 4 in N), K-chunks of 64.
template <int K, int NOUT, int USENORM>
__global__ __launch_bounds__(256) void mma_gemm(
    const __nv_bfloat16* __restrict__ Ah, const __nv_bfloat16* __restrict__ Al,
    const float* __restrict__ Af,
    const __nv_bfloat16* __restrict__ Bh, const __nv_bfloat16* __restrict__ Bl,
    float* __restrict__ C,
    const float* __restrict__ scale, const float* __restrict__ shift)
{
    constexpr int CH = K / 64;           // k-chunks
    constexpr int NT = NOUT / 32;        // n8-tiles per warp
    constexpr int BPLANE = NOUT * 128;   // bytes per B plane tile (NOUT rows x 128B)
    constexpr int STAGE = 32768 + 2 * BPLANE;
    constexpr int BATOMS = NOUT / 32;    // B cp.async atoms per thread per plane

    extern __shared__ __align__(128) char smem[];
    const uint32_t sb = smem_u32(smem);
    const int t = threadIdx.x;
    const int wid = t >> 5, lane = t & 31;
    const int warpM = (wid >> 2) * 64;          // 0 or 64
    const int warpN = (wid & 3) * (NOUT / 4);
    const int row0 = blockIdx.x * 128;
    const int b = row0 >> 13;                    // batch id

    float acc[4][NT][4];
#pragma unroll
    for (int i = 0; i < 4; ++i)
#pragma unroll
        for (int j = 0; j < NT; ++j)
#pragma unroll
            for (int q = 0; q < 4; ++q) acc[i][j][q] = 0.f;

    float va[4][8];   // USENORM staging

    auto issueB = [&](int c, int s) {
#pragma unroll
        for (int i = 0; i < BATOMS; ++i) {
            const int id = t + i * 256;
            const int n = id >> 3, a = id & 7;
            const uint32_t swo = (uint32_t)(a * 16) ^ (uint32_t)((n & 7) << 4);
            const uint32_t d = sb + s * STAGE + 32768 + n * 128 + swo;
            const size_t src = (size_t)n * K + c * 64 + a * 8;
            cpa16(d, Bh + src);
            cpa16(d + BPLANE, Bl + src);
        }
    };
    auto issueA = [&](int c, int s) {   // USENORM==0
#pragma unroll
        for (int i = 0; i < 4; ++i) {
            const int id = t + i * 256;
            const int r = id >> 3, a = id & 7;
            const uint32_t swo = (uint32_t)(a * 16) ^ (uint32_t)((r & 7) << 4);
            const uint32_t d = sb + s * STAGE + r * 128 + swo;
            const size_t src = (size_t)(row0 + r) * K + c * 64 + a * 8;
            cpa16(d, Ah + src);
            cpa16(d + 16384, Al + src);
        }
    };
    auto ldgA = [&](int c) {            // USENORM==1: load + GN fold + relu
#pragma unroll
        for (int i = 0; i < 4; ++i) {
            const int id = t + i * 256;
            const int r = id >> 3, a = id & 7;
            const float* p = Af + (size_t)(row0 + r) * K + c * 64 + a * 8;
            const float4 u = *(const float4*)p;
            const float4 v = *(const float4*)(p + 4);
            const int col = b * K + c * 64 + a * 8;
            const float4 s0 = *(const float4*)(scale + col);
            const float4 s1 = *(const float4*)(scale + col + 4);
            const float4 h0 = *(const float4*)(shift + col);
            const float4 h1 = *(const float4*)(shift + col + 4);
            va[i][0] = fmaxf(0.f, fmaf(u.x, s0.x, h0.x));
            va[i][1] = fmaxf(0.f, fmaf(u.y, s0.y, h0.y));
            va[i][2] = fmaxf(0.f, fmaf(u.z, s0.z, h0.z));
            va[i][3] = fmaxf(0.f, fmaf(u.w, s0.w, h0.w));
            va[i][4] = fmaxf(0.f, fmaf(v.x, s1.x, h1.x));
            va[i][5] = fmaxf(0.f, fmaf(v.y, s1.y, h1.y));
            va[i][6] = fmaxf(0.f, fmaf(v.z, s1.z, h1.z));
            va[i][7] = fmaxf(0.f, fmaf(v.w, s1.w, h1.w));
        }
    };
    auto stsA = [&](int s) {            // USENORM==1: split + store both planes
#pragma unroll
        for (int i = 0; i < 4; ++i) {
            const int id = t + i * 256;
            const int r = id >> 3, a = id & 7;
            uint32_t hw[4], lw[4];
#pragma unroll
            for (int q = 0; q < 4; ++q) {
                const float x0 = va[i][2 * q], x1 = va[i][2 * q + 1];
                const __nv_bfloat162 hh = __floats2bfloat162_rn(x0, x1);
                const float l0 = x0 - __bfloat162float(hh.x);
                const float l1 = x1 - __bfloat162float(hh.y);
                const __nv_bfloat162 ll = __floats2bfloat162_rn(l0, l1);
                hw[q] = bf2bits(hh);
                lw[q] = bf2bits(ll);
            }
            const uint32_t swo = (uint32_t)(a * 16) ^ (uint32_t)((r & 7) << 4);
            const uint32_t d = sb + s * STAGE + r * 128 + swo;
            asm volatile("st.shared.v4.b32 [%0], {%1,%2,%3,%4};"
                         :: "r"(d), "r"(hw[0]), "r"(hw[1]), "r"(hw[2]), "r"(hw[3]) : "memory");
            asm volatile("st.shared.v4.b32 [%0], {%1,%2,%3,%4};"
                         :: "r"(d + 16384), "r"(lw[0]), "r"(lw[1]), "r"(lw[2]), "r"(lw[3]) : "memory");
        }
    };

    // prologue
    if (USENORM) {
        ldgA(0);
        issueB(0, 0);
        CP_COMMIT();
    } else {
        issueA(0, 0);
        issueB(0, 0);
        CP_COMMIT();
    }

    for (int c = 0; c < CH; ++c) {
        const int s = c & 1;
        if (USENORM) {
            stsA(s);
            if (c + 1 < CH) { issueB(c + 1, s ^ 1); CP_COMMIT(); CP_WAIT(1); }
            else            { CP_WAIT(0); }
            __syncthreads();
            if (c + 1 < CH) ldgA(c + 1);
        } else {
            if (c + 1 < CH) {
                issueA(c + 1, s ^ 1);
                issueB(c + 1, s ^ 1);
                CP_COMMIT();
                CP_WAIT(1);
            } else {
                CP_WAIT(0);
            }
            __syncthreads();
        }

        const uint32_t aBh = sb + s * STAGE;
        const uint32_t aBl = aBh + 16384;
        const uint32_t bBh = aBh + 32768;
        const uint32_t bBl = bBh + BPLANE;

        const int rowL = lane & 15;
        const uint32_t xorA = (uint32_t)((rowL & 7) << 4);
        const uint32_t colA0 = (uint32_t)((lane >> 4) * 16);
        const int nl = ((lane >> 4) << 3) + (lane & 7);
        const uint32_t xorB = (uint32_t)((nl & 7) << 4);
        const uint32_t colB0 = (uint32_t)(((lane >> 3) & 1) * 16);

#pragma unroll
        for (int s16 = 0; s16 < 4; ++s16) {
            uint32_t afh[4][4], afl[4][4];
#pragma unroll
            for (int mt = 0; mt < 4; ++mt) {
                const uint32_t off = (uint32_t)(warpM + mt * 16 + rowL) * 128 +
                                     ((colA0 + s16 * 32) ^ xorA);
                ldsm4(afh[mt][0], afh[mt][1], afh[mt][2], afh[mt][3], aBh + off);
                ldsm4(afl[mt][0], afl[mt][1], afl[mt][2], afl[mt][3], aBl + off);
            }
#pragma unroll
            for (int np = 0; np < NT / 2; ++np) {
                const uint32_t offB = (uint32_t)(warpN + np * 16 + nl) * 128 +
                                      ((colB0 + s16 * 32) ^ xorB);
                uint32_t bh0, bh1, bh2, bh3, bl0, bl1, bl2, bl3;
                ldsm4(bh0, bh1, bh2, bh3, bBh + offB);
                ldsm4(bl0, bl1, bl2, bl3, bBl + offB);
#pragma unroll
                for (int mt = 0; mt < 4; ++mt) {
                    mma16816(acc[mt][2 * np], afh[mt], bh0, bh1);
                    mma16816(acc[mt][2 * np], afh[mt], bl0, bl1);
                    mma16816(acc[mt][2 * np], afl[mt], bh0, bh1);
                    mma16816(acc[mt][2 * np + 1], afh[mt], bh2, bh3);
                    mma16816(acc[mt][2 * np + 1], afh[mt], bl2, bl3);
                    mma16816(acc[mt][2 * np + 1], afl[mt], bh2, bh3);
                }
            }
        }
        __syncthreads();
    }

    // epilogue
    const int g = lane >> 2, tig = lane & 3;
#pragma unroll
    for (int mt = 0; mt < 4; ++mt) {
#pragma unroll
        for (int nt = 0; nt < NT; ++nt) {
            const int row = row0 + warpM + mt * 16 + g;
            const int col = warpN + nt * 8 + tig * 2;
            float2 v01 = make_float2(acc[mt][nt][0], acc[mt][nt][1]);
            float2 v23 = make_float2(acc[mt][nt][2], acc[mt][nt][3]);
            *(float2*)(C + (size_t)row * NOUT + col) = v01;
            *(float2*)(C + (size_t)(row + 8) * NOUT + col) = v23;
        }
    }
}

// ---------------- weight pre-split ------------------------------------------
__global__ __launch_bounds__(256) void prep_w_kernel(
    const float* __restrict__ w0, const float* __restrict__ w1)
{
    const int i = blockIdx.x * 256 + threadIdx.x;
    if (i < H0 * CIN) {
        const float x = w0[i];
        const __nv_bfloat16 h = __float2bfloat16(x);
        g_w0h[i] = h;
        g_w0l[i] = __float2bfloat16(x - __bfloat162float(h));
    }
    if (i < H1 * H0) {
        const float x = w1[i];
        const __nv_bfloat16 h = __float2bfloat16(x);
        g_w1h[i] = h;
        g_w1l[i] = __float2bfloat16(x - __bfloat162float(h));
    }
}

// ---------------- 3-NN + interpolate + concat (writes split planes) ---------
__device__ __forceinline__ void pack8_split(const float* x, __nv_bfloat16* ph,
                                            __nv_bfloat16* pl)
{
    uint32_t hw[4], lw[4];
#pragma unroll
    for (int q = 0; q < 4; ++q) {
        const __nv_bfloat162 hh = __floats2bfloat162_rn(x[2 * q], x[2 * q + 1]);
        const float l0 = x[2 * q] - __bfloat162float(hh.x);
        const float l1 = x[2 * q + 1] - __bfloat162float(hh.y);
        const __nv_bfloat162 ll = __floats2bfloat162_rn(l0, l1);
        hw[q] = bf2bits(hh);
        lw[q] = bf2bits(ll);
    }
    *(uint4*)ph = make_uint4(hw[0], hw[1], hw[2], hw[3]);
    *(uint4*)pl = make_uint4(lw[0], lw[1], lw[2], lw[3]);
}

__global__ __launch_bounds__(256) void knn_interp_kernel(
    const float* __restrict__ xyz1, const float* __restrict__ xyz2,
    const float* __restrict__ points1, const float* __restrict__ points2)
{
    __shared__ float4 sp[M2];   // {x,y,z,|p|^2}
    const int b = blockIdx.y;
    const float* x2 = xyz2 + (size_t)b * M2 * 3;
    for (int j = threadIdx.x; j < M2; j += 256) {
        float x = x2[j * 3 + 0], y = x2[j * 3 + 1], z = x2[j * 3 + 2];
        sp[j] = make_float4(x, y, z, x * x + y * y + z * z);
    }
    __syncthreads();

    const int n = blockIdx.x * 256 + threadIdx.x;
    const float* p1 = xyz1 + ((size_t)b * N1 + n) * 3;
    const float px = p1[0], py = p1[1], pz = p1[2];
    const float psq = px * px + py * py + pz * pz;

    float d0 = 1e30f, d1 = 1e30f, d2 = 1e30f;
    int i0 = 0, i1 = 0, i2 = 0;
#pragma unroll 4
    for (int j = 0; j < M2; ++j) {
        float4 q = sp[j];
        float tdot = fmaf(px, q.x, fmaf(py, q.y, pz * q.z));
        float d = psq + q.w - 2.0f * tdot;
        if (d < d2) {
            if (d < d1) {
                if (d < d0) { d2 = d1; i2 = i1; d1 = d0; i1 = i0; d0 = d; i0 = j; }
                else        { d2 = d1; i2 = i1; d1 = d;  i1 = j; }
            } else          { d2 = d;  i2 = j; }
        }
    }
    float w0 = 1.0f / (d0 + 1e-8f);
    float w1 = 1.0f / (d1 + 1e-8f);
    float w2 = 1.0f / (d2 + 1e-8f);
    const float inv = 1.0f / (w0 + w1 + w2);
    w0 *= inv; w1 *= inv; w2 *= inv;

    const size_t m = (size_t)b * N1 + n;
    __nv_bfloat16* fh = g_fh + m * CIN;
    __nv_bfloat16* fl = g_fl + m * CIN;
    const float* pp1 = points1 + m * C1;

    float buf[8];
#pragma unroll 4
    for (int c = 0; c < C1; c += 8) {
        const float4 u = *(const float4*)(pp1 + c);
        const float4 v = *(const float4*)(pp1 + c + 4);
        buf[0] = u.x; buf[1] = u.y; buf[2] = u.z; buf[3] = u.w;
        buf[4] = v.x; buf[5] = v.y; buf[6] = v.z; buf[7] = v.w;
        pack8_split(buf, fh + c, fl + c);
    }

    const float* r0 = points2 + ((size_t)b * M2 + i0) * C2;
    const float* r1 = points2 + ((size_t)b * M2 + i1) * C2;
    const float* r2 = points2 + ((size_t)b * M2 + i2) * C2;
#pragma unroll 4
    for (int c = 0; c < C2; c += 8) {
#pragma unroll
        for (int h = 0; h < 2; ++h) {
            const float4 a = *(const float4*)(r0 + c + h * 4);
            const float4 bb = *(const float4*)(r1 + c + h * 4);
            const float4 cc = *(const float4*)(r2 + c + h * 4);
            buf[h * 4 + 0] = w0 * a.x + w1 * bb.x + w2 * cc.x;
            buf[h * 4 + 1] = w0 * a.y + w1 * bb.y + w2 * cc.y;
            buf[h * 4 + 2] = w0 * a.z + w1 * bb.z + w2 * cc.z;
            buf[h * 4 + 3] = w0 * a.w + w1 * bb.w + w2 * cc.w;
        }
        pack8_split(buf, fh + C1 + c, fl + C1 + c);
    }
}

// ---------------- GN stats: per (batch, group) mean/var -> scale/shift ------
__global__ __launch_bounds__(256) void gn_stats_kernel(
    const float* __restrict__ X, int C, int CPG,
    const float* __restrict__ gw, const float* __restrict__ gb,
    float* __restrict__ scale, float* __restrict__ shift)
{
    const int g = blockIdx.x, b = blockIdx.y;
    const float* base = X + (size_t)b * N1 * C + g * CPG;
    float s = 0.f, ss = 0.f;
    for (int n = threadIdx.x; n < N1; n += 256) {
        const float* p = base + (size_t)n * C;
        for (int c = 0; c < CPG; c += 4) {
            float4 v = *(const float4*)(p + c);
            s  += v.x + v.y + v.z + v.w;
            ss += v.x * v.x + v.y * v.y + v.z * v.z + v.w * v.w;
        }
    }
    __shared__ float rs[32], rss[32];
#pragma unroll
    for (int o = 16; o; o >>= 1) {
        s  += __shfl_down_sync(~0u, s, o);
        ss += __shfl_down_sync(~0u, ss, o);
    }
    const int w = threadIdx.x >> 5, l = threadIdx.x & 31;
    if (l == 0) { rs[w] = s; rss[w] = ss; }
    __syncthreads();
    if (w == 0) {
        s  = (l < 8) ? rs[l]  : 0.f;
        ss = (l < 8) ? rss[l] : 0.f;
#pragma unroll
        for (int o = 4; o; o >>= 1) {
            s  += __shfl_down_sync(~0u, s, o);
            ss += __shfl_down_sync(~0u, ss, o);
        }
        if (l == 0) { rs[0] = s; rss[0] = ss; }
    }
    __syncthreads();
    if (threadIdx.x < CPG) {
        const float cnt = (float)N1 * (float)CPG;
        const float mean = rs[0] / cnt;
        const float var  = rss[0] / cnt - mean * mean;
        const float rstd = rsqrtf(var + 1e-5f);
        const int c = g * CPG + threadIdx.x;
        const float sc = rstd * gw[c];
        scale[b * C + c] = sc;
        shift[b * C + c] = gb[c] - mean * sc;
    }
}

// ---------------- final GN1 + ReLU in-place on d_out ------------------------
__global__ __launch_bounds__(256) void apply_kernel(
    float* __restrict__ out,
    const float* __restrict__ scale, const float* __restrict__ shift)
{
    const size_t i = ((size_t)blockIdx.x * 256 + threadIdx.x) * 4;
    const int c = (int)(i & (H1 - 1));
    const int b = (int)(i >> 20);
    const int idx = b * H1 + c;
    float4 v = *(float4*)(out + i);
    v.x = fmaxf(0.f, fmaf(v.x, scale[idx + 0], shift[idx + 0]));
    v.y = fmaxf(0.f, fmaf(v.y, scale[idx + 1], shift[idx + 1]));
    v.z = fmaxf(0.f, fmaf(v.z, scale[idx + 2], shift[idx + 2]));
    v.w = fmaxf(0.f, fmaf(v.w, scale[idx + 3], shift[idx + 3]));
    *(float4*)(out + i) = v;
}

// ---------------- launcher ---------------------------------------------------
extern "C" void kernel_launch(void* const* d_in, const int* in_sizes, int n_in,
                              void* d_out, int out_size)
{
    const float* xyz1    = (const float*)d_in[0];
    const float* xyz2    = (const float*)d_in[1];
    const float* points1 = (const float*)d_in[2];
    const float* points2 = (const float*)d_in[3];
    const float* w0      = (const float*)d_in[4];
    const float* w1      = (const float*)d_in[5];
    const float* gn0w    = (const float*)d_in[6];
    const float* gn0b    = (const float*)d_in[7];
    const float* gn1w    = (const float*)d_in[8];
    const float* gn1b    = (const float*)d_in[9];
    float* out = (float*)d_out;

    __nv_bfloat16 *fh, *fl, *w0h, *w0l, *w1h, *w1l;
    float *h1, *sc0, *sh0, *sc1, *sh1;
    cudaGetSymbolAddress((void**)&fh,  g_fh);
    cudaGetSymbolAddress((void**)&fl,  g_fl);
    cudaGetSymbolAddress((void**)&w0h, g_w0h);
    cudaGetSymbolAddress((void**)&w0l, g_w0l);
    cudaGetSymbolAddress((void**)&w1h, g_w1h);
    cudaGetSymbolAddress((void**)&w1l, g_w1l);
    cudaGetSymbolAddress((void**)&h1,  g_h1);
    cudaGetSymbolAddress((void**)&sc0, g_scale0);
    cudaGetSymbolAddress((void**)&sh0, g_shift0);
    cudaGetSymbolAddress((void**)&sc1, g_scale1);
    cudaGetSymbolAddress((void**)&sh1, g_shift1);

    // smem: 2 stages x (A 32KB + B 2*NOUT*128B)
    const int SMEM1 = 2 * (32768 + 2 * H0 * 128);  // 196608
    const int SMEM2 = 2 * (32768 + 2 * H1 * 128);  // 131072
    cudaFuncSetAttribute(mma_gemm<CIN, H0, 0>,
                         cudaFuncAttributeMaxDynamicSharedMemorySize, SMEM1);
    cudaFuncSetAttribute(mma_gemm<H0, H1, 1>,
                         cudaFuncAttributeMaxDynamicSharedMemorySize, SMEM2);

    // 0) pre-split weights into bf16 hi/lo planes
    prep_w_kernel<<<(H0 * CIN + 255) / 256, 256>>>(w0, w1);

    // 1) 3-NN interpolate + concat -> split feat planes (65536 x 384 bf16 x2)
    knn_interp_kernel<<<dim3(N1 / 256, BB), 256>>>(xyz1, xyz2, points1, points2);

    // 2) h1 = feat @ w0^T  via bf16 split-2 mma.sync
    mma_gemm<CIN, H0, 0><<<NPTS / 128, 256, SMEM1>>>(
        fh, fl, nullptr, w0h, w0l, h1, nullptr, nullptr);

    // 3) GN0 stats -> folded scale/shift per (b, channel)
    gn_stats_kernel<<<dim3(32, BB), 256>>>(h1, H0, H0 / 32, gn0w, gn0b, sc0, sh0);

    // 4) out = relu(gn0(h1)) @ w1^T (GN0+ReLU folded at A-load, split in regs)
    mma_gemm<H0, H1, 1><<<NPTS / 128, 256, SMEM2>>>(
        nullptr, nullptr, h1, w1h, w1l, out, sc0, sh0);

    // 5) GN1 stats on out
    gn_stats_kernel<<<dim3(32, BB), 256>>>(out, H1, H1 / 32, gn1w, gn1b, sc1, sh1);

    // 6) GN1 + ReLU in-place
    apply_kernel<<<(NPTS * H1) / (256 * 4), 256>>>(out, sc1, sh1);
}

// round 4
// speedup vs baseline: 2.0869x; 1.0573x over previous
#include <cuda_runtime.h>
#include <cuda_bf16.h>
#include <cstdint>
#include <cstddef>

// Problem constants (fixed by setup_inputs)
#define BB    8
#define N1    8192
#define M2    2048
#define C1    128
#define C2    256
#define CIN   384
#define H0    256
#define H1    128
#define NPTS  (BB * N1)   // 65536

// ---------------- scratch (device globals; no allocations allowed) ----------
__device__ __align__(16) __nv_bfloat16 g_fh[(size_t)NPTS * CIN];   // feat hi plane
__device__ __align__(16) __nv_bfloat16 g_fl[(size_t)NPTS * CIN];   // feat lo plane
__device__ __align__(16) __nv_bfloat16 g_w0h[H0 * CIN];
__device__ __align__(16) __nv_bfloat16 g_w0l[H0 * CIN];
__device__ __align__(16) __nv_bfloat16 g_w1h[H1 * H0];
__device__ __align__(16) __nv_bfloat16 g_w1l[H1 * H0];
__device__ float g_h1[(size_t)NPTS * H0];      // ~67 MB
__device__ float g_scale0[BB * H0];
__device__ float g_shift0[BB * H0];
__device__ float g_scale1[BB * H1];
__device__ float g_shift1[BB * H1];
__device__ float g_s0[BB * H0];                // per-channel sums (GEMM1 out)
__device__ float g_q0[BB * H0];
__device__ float g_s1[BB * H1];                // per-channel sums (GEMM2 out)
__device__ float g_q1[BB * H1];

// ---------------- PTX helpers ------------------------------------------------
__device__ __forceinline__ uint32_t smem_u32(const void* p) {
    uint32_t a;
    asm("{ .reg .u64 t; cvta.to.shared.u64 t, %1; cvt.u32.u64 %0, t; }"
        : "=r"(a) : "l"(p));
    return a;
}
__device__ __forceinline__ void cpa16(uint32_t dst, const void* src) {
    asm volatile("cp.async.cg.shared.global [%0], [%1], 16;"
                 :: "r"(dst), "l"(src) : "memory");
}
#define CP_COMMIT() asm volatile("cp.async.commit_group;" ::: "memory")
#define CP_WAIT(n)  asm volatile("cp.async.wait_group %0;" :: "n"(n) : "memory")

__device__ __forceinline__ void ldsm4(uint32_t& r0, uint32_t& r1,
                                      uint32_t& r2, uint32_t& r3, uint32_t a) {
    asm volatile("ldmatrix.sync.aligned.m8n8.x4.shared.b16 {%0,%1,%2,%3}, [%4];"
                 : "=r"(r0), "=r"(r1), "=r"(r2), "=r"(r3) : "r"(a));
}
__device__ __forceinline__ void mma16816(float* c, const uint32_t* a,
                                         uint32_t b0, uint32_t b1) {
    asm volatile(
        "mma.sync.aligned.m16n8k16.row.col.f32.bf16.bf16.f32 "
        "{%0,%1,%2,%3}, {%4,%5,%6,%7}, {%8,%9}, {%0,%1,%2,%3};"
        : "+f"(c[0]), "+f"(c[1]), "+f"(c[2]), "+f"(c[3])
        : "r"(a[0]), "r"(a[1]), "r"(a[2]), "r"(a[3]), "r"(b0), "r"(b1));
}
__device__ __forceinline__ uint32_t bf2bits(__nv_bfloat162 v) {
    return *reinterpret_cast<uint32_t*>(&v);
}

// ---------------- bf16 split-2 GEMM on mma.sync + fused GN stats ------------
// C[m,n] = sum_k A'[m,k] * W[n,k]; also accumulates per-(batch,channel)
// sum / sumsq of C into statS/statQ via block partials + global atomics.
// USENORM==0: A pre-split bf16 planes (Ah, Al); cp.async path.
// USENORM==1: A fp32 (Af); relu(A*scale+shift) folded at load, split in regs.
template <int K, int NOUT, int USENORM>
__global__ __launch_bounds__(256) void mma_gemm(
    const __nv_bfloat16* __restrict__ Ah, const __nv_bfloat16* __restrict__ Al,
    const float* __restrict__ Af,
    const __nv_bfloat16* __restrict__ Bh, const __nv_bfloat16* __restrict__ Bl,
    float* __restrict__ C,
    const float* __restrict__ scale, const float* __restrict__ shift,
    float* __restrict__ statS, float* __restrict__ statQ)
{
    constexpr int CH = K / 64;           // k-chunks
    constexpr int NT = NOUT / 32;        // n8-tiles per warp
    constexpr int BPLANE = NOUT * 128;   // bytes per B plane tile
    constexpr int STAGE = 32768 + 2 * BPLANE;
    constexpr int BATOMS = NOUT / 32;

    extern __shared__ __align__(128) char smem[];
    const uint32_t sb = smem_u32(smem);
    float* sS = (float*)(smem + 2 * STAGE);          // [NOUT]
    float* sQ = sS + NOUT;                           // [NOUT]
    const int t = threadIdx.x;
    const int wid = t >> 5, lane = t & 31;
    const int warpM = (wid >> 2) * 64;
    const int warpN = (wid & 3) * (NOUT / 4);
    const int row0 = blockIdx.x * 128;
    const int b = row0 >> 13;

    if (t < NOUT) { sS[t] = 0.f; sQ[t] = 0.f; }

    float acc[4][NT][4];
#pragma unroll
    for (int i = 0; i < 4; ++i)
#pragma unroll
        for (int j = 0; j < NT; ++j)
#pragma unroll
            for (int q = 0; q < 4; ++q) acc[i][j][q] = 0.f;

    float va[4][8];

    auto issueB = [&](int c, int s) {
#pragma unroll
        for (int i = 0; i < BATOMS; ++i) {
            const int id = t + i * 256;
            const int n = id >> 3, a = id & 7;
            const uint32_t swo = (uint32_t)(a * 16) ^ (uint32_t)((n & 7) << 4);
            const uint32_t d = sb + s * STAGE + 32768 + n * 128 + swo;
            const size_t src = (size_t)n * K + c * 64 + a * 8;
            cpa16(d, Bh + src);
            cpa16(d + BPLANE, Bl + src);
        }
    };
    auto issueA = [&](int c, int s) {
#pragma unroll
        for (int i = 0; i < 4; ++i) {
            const int id = t + i * 256;
            const int r = id >> 3, a = id & 7;
            const uint32_t swo = (uint32_t)(a * 16) ^ (uint32_t)((r & 7) << 4);
            const uint32_t d = sb + s * STAGE + r * 128 + swo;
            const size_t src = (size_t)(row0 + r) * K + c * 64 + a * 8;
            cpa16(d, Ah + src);
            cpa16(d + 16384, Al + src);
        }
    };
    auto ldgA = [&](int c) {
#pragma unroll
        for (int i = 0; i < 4; ++i) {
            const int id = t + i * 256;
            const int r = id >> 3, a = id & 7;
            const float* p = Af + (size_t)(row0 + r) * K + c * 64 + a * 8;
            const float4 u = *(const float4*)p;
            const float4 v = *(const float4*)(p + 4);
            const int col = b * K + c * 64 + a * 8;
            const float4 s0 = *(const float4*)(scale + col);
            const float4 s1 = *(const float4*)(scale + col + 4);
            const float4 h0 = *(const float4*)(shift + col);
            const float4 h1 = *(const float4*)(shift + col + 4);
            va[i][0] = fmaxf(0.f, fmaf(u.x, s0.x, h0.x));
            va[i][1] = fmaxf(0.f, fmaf(u.y, s0.y, h0.y));
            va[i][2] = fmaxf(0.f, fmaf(u.z, s0.z, h0.z));
            va[i][3] = fmaxf(0.f, fmaf(u.w, s0.w, h0.w));
            va[i][4] = fmaxf(0.f, fmaf(v.x, s1.x, h1.x));
            va[i][5] = fmaxf(0.f, fmaf(v.y, s1.y, h1.y));
            va[i][6] = fmaxf(0.f, fmaf(v.z, s1.z, h1.z));
            va[i][7] = fmaxf(0.f, fmaf(v.w, s1.w, h1.w));
        }
    };
    auto stsA = [&](int s) {
#pragma unroll
        for (int i = 0; i < 4; ++i) {
            const int id = t + i * 256;
            const int r = id >> 3, a = id & 7;
            uint32_t hw[4], lw[4];
#pragma unroll
            for (int q = 0; q < 4; ++q) {
                const float x0 = va[i][2 * q], x1 = va[i][2 * q + 1];
                const __nv_bfloat162 hh = __floats2bfloat162_rn(x0, x1);
                const float l0 = x0 - __bfloat162float(hh.x);
                const float l1 = x1 - __bfloat162float(hh.y);
                const __nv_bfloat162 ll = __floats2bfloat162_rn(l0, l1);
                hw[q] = bf2bits(hh);
                lw[q] = bf2bits(ll);
            }
            const uint32_t swo = (uint32_t)(a * 16) ^ (uint32_t)((r & 7) << 4);
            const uint32_t d = sb + s * STAGE + r * 128 + swo;
            asm volatile("st.shared.v4.b32 [%0], {%1,%2,%3,%4};"
                         :: "r"(d), "r"(hw[0]), "r"(hw[1]), "r"(hw[2]), "r"(hw[3]) : "memory");
            asm volatile("st.shared.v4.b32 [%0], {%1,%2,%3,%4};"
                         :: "r"(d + 16384), "r"(lw[0]), "r"(lw[1]), "r"(lw[2]), "r"(lw[3]) : "memory");
        }
    };

    if (USENORM) {
        ldgA(0);
        issueB(0, 0);
        CP_COMMIT();
    } else {
        issueA(0, 0);
        issueB(0, 0);
        CP_COMMIT();
    }

    for (int c = 0; c < CH; ++c) {
        const int s = c & 1;
        if (USENORM) {
            stsA(s);
            if (c + 1 < CH) { issueB(c + 1, s ^ 1); CP_COMMIT(); CP_WAIT(1); }
            else            { CP_WAIT(0); }
            __syncthreads();
            if (c + 1 < CH) ldgA(c + 1);
        } else {
            if (c + 1 < CH) {
                issueA(c + 1, s ^ 1);
                issueB(c + 1, s ^ 1);
                CP_COMMIT();
                CP_WAIT(1);
            } else {
                CP_WAIT(0);
            }
            __syncthreads();
        }

        const uint32_t aBh = sb + s * STAGE;
        const uint32_t aBl = aBh + 16384;
        const uint32_t bBh = aBh + 32768;
        const uint32_t bBl = bBh + BPLANE;

        const int rowL = lane & 15;
        const uint32_t xorA = (uint32_t)((rowL & 7) << 4);
        const uint32_t colA0 = (uint32_t)((lane >> 4) * 16);
        const int nl = ((lane >> 4) << 3) + (lane & 7);
        const uint32_t xorB = (uint32_t)((nl & 7) << 4);
        const uint32_t colB0 = (uint32_t)(((lane >> 3) & 1) * 16);

#pragma unroll
        for (int s16 = 0; s16 < 4; ++s16) {
            uint32_t afh[4][4], afl[4][4];
#pragma unroll
            for (int mt = 0; mt < 4; ++mt) {
                const uint32_t off = (uint32_t)(warpM + mt * 16 + rowL) * 128 +
                                     ((colA0 + s16 * 32) ^ xorA);
                ldsm4(afh[mt][0], afh[mt][1], afh[mt][2], afh[mt][3], aBh + off);
                ldsm4(afl[mt][0], afl[mt][1], afl[mt][2], afl[mt][3], aBl + off);
            }
#pragma unroll
            for (int np = 0; np < NT / 2; ++np) {
                const uint32_t offB = (uint32_t)(warpN + np * 16 + nl) * 128 +
                                      ((colB0 + s16 * 32) ^ xorB);
                uint32_t bh0, bh1, bh2, bh3, bl0, bl1, bl2, bl3;
                ldsm4(bh0, bh1, bh2, bh3, bBh + offB);
                ldsm4(bl0, bl1, bl2, bl3, bBl + offB);
#pragma unroll
                for (int mt = 0; mt < 4; ++mt) {
                    mma16816(acc[mt][2 * np], afh[mt], bh0, bh1);
                    mma16816(acc[mt][2 * np], afh[mt], bl0, bl1);
                    mma16816(acc[mt][2 * np], afl[mt], bh0, bh1);
                    mma16816(acc[mt][2 * np + 1], afh[mt], bh2, bh3);
                    mma16816(acc[mt][2 * np + 1], afh[mt], bl2, bl3);
                    mma16816(acc[mt][2 * np + 1], afl[mt], bh2, bh3);
                }
            }
        }
        __syncthreads();
    }

    // epilogue: write C + per-column stats
    const int g = lane >> 2, tig = lane & 3;
#pragma unroll
    for (int mt = 0; mt < 4; ++mt) {
#pragma unroll
        for (int nt = 0; nt < NT; ++nt) {
            const int row = row0 + warpM + mt * 16 + g;
            const int col = warpN + nt * 8 + tig * 2;
            float2 v01 = make_float2(acc[mt][nt][0], acc[mt][nt][1]);
            float2 v23 = make_float2(acc[mt][nt][2], acc[mt][nt][3]);
            *(float2*)(C + (size_t)row * NOUT + col) = v01;
            *(float2*)(C + (size_t)(row + 8) * NOUT + col) = v23;
        }
    }
#pragma unroll
    for (int nt = 0; nt < NT; ++nt) {
        float s0 = 0.f, s1 = 0.f, q0 = 0.f, q1 = 0.f;
#pragma unroll
        for (int mt = 0; mt < 4; ++mt) {
            const float a0 = acc[mt][nt][0], a1 = acc[mt][nt][1];
            const float a2 = acc[mt][nt][2], a3 = acc[mt][nt][3];
            s0 += a0 + a2;         s1 += a1 + a3;
            q0 += a0 * a0 + a2 * a2;
            q1 += a1 * a1 + a3 * a3;
        }
#pragma unroll
        for (int o = 4; o < 32; o <<= 1) {
            s0 += __shfl_xor_sync(~0u, s0, o);
            s1 += __shfl_xor_sync(~0u, s1, o);
            q0 += __shfl_xor_sync(~0u, q0, o);
            q1 += __shfl_xor_sync(~0u, q1, o);
        }
        if (g == 0) {
            const int col = warpN + nt * 8 + tig * 2;
            atomicAdd(&sS[col], s0);     atomicAdd(&sS[col + 1], s1);
            atomicAdd(&sQ[col], q0);     atomicAdd(&sQ[col + 1], q1);
        }
    }
    __syncthreads();
    if (t < NOUT) {
        atomicAdd(statS + b * NOUT + t, sS[t]);
        atomicAdd(statQ + b * NOUT + t, sQ[t]);
    }
}

// ---------------- gn scale/shift from accumulated sums ----------------------
__global__ void gn_scale_kernel(
    const float* __restrict__ gS, const float* __restrict__ gQ,
    const float* __restrict__ gw, const float* __restrict__ gb,
    float* __restrict__ scale, float* __restrict__ shift, int C, int CPG)
{
    const int g = blockIdx.x, b = blockIdx.y, l = threadIdx.x;
    float s = 0.f, q = 0.f;
    if (l < CPG) {
        s = gS[b * C + g * CPG + l];
        q = gQ[b * C + g * CPG + l];
    }
#pragma unroll
    for (int o = 16; o; o >>= 1) {
        s += __shfl_down_sync(~0u, s, o);
        q += __shfl_down_sync(~0u, q, o);
    }
    s = __shfl_sync(~0u, s, 0);
    q = __shfl_sync(~0u, q, 0);
    if (l < CPG) {
        const float cnt = (float)N1 * (float)CPG;
        const float mean = s / cnt;
        const float var  = q / cnt - mean * mean;
        const float rstd = rsqrtf(var + 1e-5f);
        const int c = g * CPG + l;
        const float sc = rstd * gw[c];
        scale[b * C + c] = sc;
        shift[b * C + c] = gb[c] - mean * sc;
    }
}

// ---------------- weight pre-split + stat accumulator zero ------------------
__global__ __launch_bounds__(256) void prep_w_kernel(
    const float* __restrict__ w0, const float* __restrict__ w1)
{
    const int i = blockIdx.x * 256 + threadIdx.x;
    if (i < H0 * CIN) {
        const float x = w0[i];
        const __nv_bfloat16 h = __float2bfloat16(x);
        g_w0h[i] = h;
        g_w0l[i] = __float2bfloat16(x - __bfloat162float(h));
    }
    if (i < H1 * H0) {
        const float x = w1[i];
        const __nv_bfloat16 h = __float2bfloat16(x);
        g_w1h[i] = h;
        g_w1l[i] = __float2bfloat16(x - __bfloat162float(h));
    }
    if (i < BB * H0) { g_s0[i] = 0.f; g_q0[i] = 0.f; }
    if (i < BB * H1) { g_s1[i] = 0.f; g_q1[i] = 0.f; }
}

// ---------------- 3-NN + interpolate + concat (writes split planes) ---------
__device__ __forceinline__ void pack8_split(const float* x, __nv_bfloat16* ph,
                                            __nv_bfloat16* pl)
{
    uint32_t hw[4], lw[4];
#pragma unroll
    for (int q = 0; q < 4; ++q) {
        const __nv_bfloat162 hh = __floats2bfloat162_rn(x[2 * q], x[2 * q + 1]);
        const float l0 = x[2 * q] - __bfloat162float(hh.x);
        const float l1 = x[2 * q + 1] - __bfloat162float(hh.y);
        const __nv_bfloat162 ll = __floats2bfloat162_rn(l0, l1);
        hw[q] = bf2bits(hh);
        lw[q] = bf2bits(ll);
    }
    *(uint4*)ph = make_uint4(hw[0], hw[1], hw[2], hw[3]);
    *(uint4*)pl = make_uint4(lw[0], lw[1], lw[2], lw[3]);
}

__global__ __launch_bounds__(256) void knn_interp_kernel(
    const float* __restrict__ xyz1, const float* __restrict__ xyz2,
    const float* __restrict__ points1, const float* __restrict__ points2)
{
    __shared__ float4 sp[M2];
    const int b = blockIdx.y;
    const float* x2 = xyz2 + (size_t)b * M2 * 3;
    for (int j = threadIdx.x; j < M2; j += 256) {
        float x = x2[j * 3 + 0], y = x2[j * 3 + 1], z = x2[j * 3 + 2];
        sp[j] = make_float4(x, y, z, x * x + y * y + z * z);
    }
    __syncthreads();

    const int n = blockIdx.x * 256 + threadIdx.x;
    const float* p1 = xyz1 + ((size_t)b * N1 + n) * 3;
    const float px = p1[0], py = p1[1], pz = p1[2];
    const float psq = px * px + py * py + pz * pz;

    float d0 = 1e30f, d1 = 1e30f, d2 = 1e30f;
    int i0 = 0, i1 = 0, i2 = 0;
#pragma unroll 4
    for (int j = 0; j < M2; ++j) {
        float4 q = sp[j];
        float tdot = fmaf(px, q.x, fmaf(py, q.y, pz * q.z));
        float d = psq + q.w - 2.0f * tdot;
        if (d < d2) {
            if (d < d1) {
                if (d < d0) { d2 = d1; i2 = i1; d1 = d0; i1 = i0; d0 = d; i0 = j; }
                else        { d2 = d1; i2 = i1; d1 = d;  i1 = j; }
            } else          { d2 = d;  i2 = j; }
        }
    }
    float w0 = 1.0f / (d0 + 1e-8f);
    float w1 = 1.0f / (d1 + 1e-8f);
    float w2 = 1.0f / (d2 + 1e-8f);
    const float inv = 1.0f / (w0 + w1 + w2);
    w0 *= inv; w1 *= inv; w2 *= inv;

    const size_t m = (size_t)b * N1 + n;
    __nv_bfloat16* fh = g_fh + m * CIN;
    __nv_bfloat16* fl = g_fl + m * CIN;
    const float* pp1 = points1 + m * C1;

    float buf[8];
#pragma unroll 4
    for (int c = 0; c < C1; c += 8) {
        const float4 u = *(const float4*)(pp1 + c);
        const float4 v = *(const float4*)(pp1 + c + 4);
        buf[0] = u.x; buf[1] = u.y; buf[2] = u.z; buf[3] = u.w;
        buf[4] = v.x; buf[5] = v.y; buf[6] = v.z; buf[7] = v.w;
        pack8_split(buf, fh + c, fl + c);
    }

    const float* r0 = points2 + ((size_t)b * M2 + i0) * C2;
    const float* r1 = points2 + ((size_t)b * M2 + i1) * C2;
    const float* r2 = points2 + ((size_t)b * M2 + i2) * C2;
#pragma unroll 4
    for (int c = 0; c < C2; c += 8) {
#pragma unroll
        for (int h = 0; h < 2; ++h) {
            const float4 a = *(const float4*)(r0 + c + h * 4);
            const float4 bb = *(const float4*)(r1 + c + h * 4);
            const float4 cc = *(const float4*)(r2 + c + h * 4);
            buf[h * 4 + 0] = w0 * a.x + w1 * bb.x + w2 * cc.x;
            buf[h * 4 + 1] = w0 * a.y + w1 * bb.y + w2 * cc.y;
            buf[h * 4 + 2] = w0 * a.z + w1 * bb.z + w2 * cc.z;
            buf[h * 4 + 3] = w0 * a.w + w1 * bb.w + w2 * cc.w;
        }
        pack8_split(buf, fh + C1 + c, fl + C1 + c);
    }
}

// ---------------- final GN1 + ReLU in-place on d_out ------------------------
__global__ __launch_bounds__(256) void apply_kernel(
    float* __restrict__ out,
    const float* __restrict__ scale, const float* __restrict__ shift)
{
    const size_t i = ((size_t)blockIdx.x * 256 + threadIdx.x) * 4;
    const int c = (int)(i & (H1 - 1));
    const int b = (int)(i >> 20);
    const int idx = b * H1 + c;
    float4 v = *(float4*)(out + i);
    v.x = fmaxf(0.f, fmaf(v.x, scale[idx + 0], shift[idx + 0]));
    v.y = fmaxf(0.f, fmaf(v.y, scale[idx + 1], shift[idx + 1]));
    v.z = fmaxf(0.f, fmaf(v.z, scale[idx + 2], shift[idx + 2]));
    v.w = fmaxf(0.f, fmaf(v.w, scale[idx + 3], shift[idx + 3]));
    *(float4*)(out + i) = v;
}

// ---------------- launcher ---------------------------------------------------
extern "C" void kernel_launch(void* const* d_in, const int* in_sizes, int n_in,
                              void* d_out, int out_size)
{
    const float* xyz1    = (const float*)d_in[0];
    const float* xyz2    = (const float*)d_in[1];
    const float* points1 = (const float*)d_in[2];
    const float* points2 = (const float*)d_in[3];
    const float* w0      = (const float*)d_in[4];
    const float* w1      = (const float*)d_in[5];
    const float* gn0w    = (const float*)d_in[6];
    const float* gn0b    = (const float*)d_in[7];
    const float* gn1w    = (const float*)d_in[8];
    const float* gn1b    = (const float*)d_in[9];
    float* out = (float*)d_out;

    __nv_bfloat16 *fh, *fl, *w0h, *w0l, *w1h, *w1l;
    float *h1, *sc0, *sh0, *sc1, *sh1, *s0, *q0, *s1, *q1;
    cudaGetSymbolAddress((void**)&fh,  g_fh);
    cudaGetSymbolAddress((void**)&fl,  g_fl);
    cudaGetSymbolAddress((void**)&w0h, g_w0h);
    cudaGetSymbolAddress((void**)&w0l, g_w0l);
    cudaGetSymbolAddress((void**)&w1h, g_w1h);
    cudaGetSymbolAddress((void**)&w1l, g_w1l);
    cudaGetSymbolAddress((void**)&h1,  g_h1);
    cudaGetSymbolAddress((void**)&sc0, g_scale0);
    cudaGetSymbolAddress((void**)&sh0, g_shift0);
    cudaGetSymbolAddress((void**)&sc1, g_scale1);
    cudaGetSymbolAddress((void**)&sh1, g_shift1);
    cudaGetSymbolAddress((void**)&s0,  g_s0);
    cudaGetSymbolAddress((void**)&q0,  g_q0);
    cudaGetSymbolAddress((void**)&s1,  g_s1);
    cudaGetSymbolAddress((void**)&q1,  g_q1);

    // smem: 2 stages x (A 32KB + B 2*NOUT*128B) + stats (2*NOUT floats)
    const int SMEM1 = 2 * (32768 + 2 * H0 * 128) + 2 * H0 * 4;  // 198656
    const int SMEM2 = 2 * (32768 + 2 * H1 * 128) + 2 * H1 * 4;  // 132096
    cudaFuncSetAttribute(mma_gemm<CIN, H0, 0>,
                         cudaFuncAttributeMaxDynamicSharedMemorySize, SMEM1);
    cudaFuncSetAttribute(mma_gemm<H0, H1, 1>,
                         cudaFuncAttributeMaxDynamicSharedMemorySize, SMEM2);

    // 0) pre-split weights; zero stat accumulators (graph-replay safe)
    prep_w_kernel<<<(H0 * CIN + 255) / 256, 256>>>(w0, w1);

    // 1) 3-NN interpolate + concat -> split feat planes
    knn_interp_kernel<<<dim3(N1 / 256, BB), 256>>>(xyz1, xyz2, points1, points2);

    // 2) h1 = feat @ w0^T, with fused GN0 stat accumulation
    mma_gemm<CIN, H0, 0><<<NPTS / 128, 256, SMEM1>>>(
        fh, fl, nullptr, w0h, w0l, h1, nullptr, nullptr, s0, q0);

    // 3) fold GN0 stats -> scale/shift
    gn_scale_kernel<<<dim3(32, BB), 32>>>(s0, q0, gn0w, gn0b, sc0, sh0, H0, H0 / 32);

    // 4) out = relu(gn0(h1)) @ w1^T, with fused GN1 stat accumulation
    mma_gemm<H0, H1, 1><<<NPTS / 128, 256, SMEM2>>>(
        nullptr, nullptr, h1, w1h, w1l, out, sc0, sh0, s1, q1);

    // 5) fold GN1 stats -> scale/shift
    gn_scale_kernel<<<dim3(32, BB), 32>>>(s1, q1, gn1w, gn1b, sc1, sh1, H1, H1 / 32);

    // 6) GN1 + ReLU in-place
    apply_kernel<<<(NPTS * H1) / (256 * 4), 256>>>(out, sc1, sh1);
}

// round 5
// speedup vs baseline: 2.1353x; 1.0232x over previous
#include <cuda_runtime.h>
#include <cuda_bf16.h>
#include <cstdint>
#include <cstddef>

// Problem constants (fixed by setup_inputs)
#define BB    8
#define N1    8192
#define M2    2048
#define C1    128
#define C2    256
#define CIN   384
#define H0    256
#define H1    128
#define NPTS  (BB * N1)   // 65536

// ---------------- scratch (device globals; no allocations allowed) ----------
__device__ __align__(16) __nv_bfloat16 g_fh[(size_t)NPTS * CIN];
__device__ __align__(16) __nv_bfloat16 g_fl[(size_t)NPTS * CIN];
__device__ __align__(16) __nv_bfloat16 g_w0h[H0 * CIN];
__device__ __align__(16) __nv_bfloat16 g_w0l[H0 * CIN];
__device__ __align__(16) __nv_bfloat16 g_w1h[H1 * H0];
__device__ __align__(16) __nv_bfloat16 g_w1l[H1 * H0];
__device__ float g_h1[(size_t)NPTS * H0];
__device__ float g_scale0[BB * H0];
__device__ float g_shift0[BB * H0];
__device__ float g_scale1[BB * H1];
__device__ float g_shift1[BB * H1];
__device__ float g_s0[BB * H0];
__device__ float g_q0[BB * H0];
__device__ float g_s1[BB * H1];
__device__ float g_q1[BB * H1];
__device__ int   g_cnt0[BB];
__device__ int   g_cnt1[BB];

// ---------------- PTX helpers ------------------------------------------------
__device__ __forceinline__ uint32_t smem_u32(const void* p) {
    uint32_t a;
    asm("{ .reg .u64 t; cvta.to.shared.u64 t, %1; cvt.u32.u64 %0, t; }"
        : "=r"(a) : "l"(p));
    return a;
}
__device__ __forceinline__ void cpa16(uint32_t dst, const void* src) {
    asm volatile("cp.async.cg.shared.global [%0], [%1], 16;"
                 :: "r"(dst), "l"(src) : "memory");
}
#define CP_COMMIT() asm volatile("cp.async.commit_group;" ::: "memory")
#define CP_WAIT(n)  asm volatile("cp.async.wait_group %0;" :: "n"(n) : "memory")

__device__ __forceinline__ void ldsm4(uint32_t& r0, uint32_t& r1,
                                      uint32_t& r2, uint32_t& r3, uint32_t a) {
    asm volatile("ldmatrix.sync.aligned.m8n8.x4.shared.b16 {%0,%1,%2,%3}, [%4];"
                 : "=r"(r0), "=r"(r1), "=r"(r2), "=r"(r3) : "r"(a));
}
__device__ __forceinline__ void mma16816(float* c, const uint32_t* a,
                                         uint32_t b0, uint32_t b1) {
    asm volatile(
        "mma.sync.aligned.m16n8k16.row.col.f32.bf16.bf16.f32 "
        "{%0,%1,%2,%3}, {%4,%5,%6,%7}, {%8,%9}, {%0,%1,%2,%3};"
        : "+f"(c[0]), "+f"(c[1]), "+f"(c[2]), "+f"(c[3])
        : "r"(a[0]), "r"(a[1]), "r"(a[2]), "r"(a[3]), "r"(b0), "r"(b1));
}
__device__ __forceinline__ uint32_t bf2bits(__nv_bfloat162 v) {
    return *reinterpret_cast<uint32_t*>(&v);
}

// ---------------- bf16 split-2 GEMM + fused GN stats + fused scale ----------
// 512 threads, block tile 128 x NOUT, K-chunks of 64.
// USENORM==0: A pre-split bf16 planes (cp.async); USENORM==1: A fp32, GN-fold
// + relu + split at load. Epilogue: per-(batch,channel) sum/sumsq atomics;
// the LAST block of each batch computes scale/shift for the NEXT stage.
template <int K, int NOUT, int USENORM>
__global__ __launch_bounds__(512, 1) void mma_gemm(
    const __nv_bfloat16* __restrict__ Ah, const __nv_bfloat16* __restrict__ Al,
    const float* __restrict__ Af,
    const __nv_bfloat16* __restrict__ Bh, const __nv_bfloat16* __restrict__ Bl,
    float* __restrict__ C,
    const float* __restrict__ scale, const float* __restrict__ shift,
    float* __restrict__ statS, float* __restrict__ statQ,
    const float* __restrict__ gw, const float* __restrict__ gb,
    float* __restrict__ oScale, float* __restrict__ oShift,
    int* __restrict__ counter)
{
    constexpr int CH = K / 64;
    constexpr int WN = NOUT / 8;         // columns per warp
    constexpr int NT = WN / 8;           // n8-tiles per warp (4 or 2)
    constexpr int BPLANE = NOUT * 128;
    constexpr int STAGE = 32768 + 2 * BPLANE;
    constexpr int BITER = NOUT / 64;     // B cp.async iters (2 planes each)
    constexpr int CPG = NOUT / 32;       // channels per GN group

    extern __shared__ __align__(128) char smem[];
    const uint32_t sb = smem_u32(smem);
    float* sS = (float*)(smem + 2 * STAGE);
    float* sQ = sS + NOUT;
    const int t = threadIdx.x;
    const int wid = t >> 5, lane = t & 31;
    const int warpM = (wid >> 3) * 64;          // 0 or 64
    const int warpN = (wid & 7) * WN;
    const int row0 = blockIdx.x * 128;
    const int b = row0 >> 13;

    if (t < NOUT) { sS[t] = 0.f; sQ[t] = 0.f; }

    float acc[4][NT][4];
#pragma unroll
    for (int i = 0; i < 4; ++i)
#pragma unroll
        for (int j = 0; j < NT; ++j)
#pragma unroll
            for (int q = 0; q < 4; ++q) acc[i][j][q] = 0.f;

    float va[2][8];

    auto issueB = [&](int c, int s) {
#pragma unroll
        for (int i = 0; i < BITER; ++i) {
            const int id = t + i * 512;
            const int n = id >> 3, a = id & 7;
            const uint32_t swo = (uint32_t)(a * 16) ^ (uint32_t)((n & 7) << 4);
            const uint32_t d = sb + s * STAGE + 32768 + n * 128 + swo;
            const size_t src = (size_t)n * K + c * 64 + a * 8;
            cpa16(d, Bh + src);
            cpa16(d + BPLANE, Bl + src);
        }
    };
    auto issueA = [&](int c, int s) {
#pragma unroll
        for (int i = 0; i < 2; ++i) {
            const int id = t + i * 512;
            const int r = id >> 3, a = id & 7;
            const uint32_t swo = (uint32_t)(a * 16) ^ (uint32_t)((r & 7) << 4);
            const uint32_t d = sb + s * STAGE + r * 128 + swo;
            const size_t src = (size_t)(row0 + r) * K + c * 64 + a * 8;
            cpa16(d, Ah + src);
            cpa16(d + 16384, Al + src);
        }
    };
    auto ldgA = [&](int c) {
#pragma unroll
        for (int i = 0; i < 2; ++i) {
            const int id = t + i * 512;
            const int r = id >> 3, a = id & 7;
            const float* p = Af + (size_t)(row0 + r) * K + c * 64 + a * 8;
            const float4 u = *(const float4*)p;
            const float4 v = *(const float4*)(p + 4);
            const int col = b * K + c * 64 + a * 8;
            const float4 s0 = *(const float4*)(scale + col);
            const float4 s1 = *(const float4*)(scale + col + 4);
            const float4 h0 = *(const float4*)(shift + col);
            const float4 h1 = *(const float4*)(shift + col + 4);
            va[i][0] = fmaxf(0.f, fmaf(u.x, s0.x, h0.x));
            va[i][1] = fmaxf(0.f, fmaf(u.y, s0.y, h0.y));
            va[i][2] = fmaxf(0.f, fmaf(u.z, s0.z, h0.z));
            va[i][3] = fmaxf(0.f, fmaf(u.w, s0.w, h0.w));
            va[i][4] = fmaxf(0.f, fmaf(v.x, s1.x, h1.x));
            va[i][5] = fmaxf(0.f, fmaf(v.y, s1.y, h1.y));
            va[i][6] = fmaxf(0.f, fmaf(v.z, s1.z, h1.z));
            va[i][7] = fmaxf(0.f, fmaf(v.w, s1.w, h1.w));
        }
    };
    auto stsA = [&](int s) {
#pragma unroll
        for (int i = 0; i < 2; ++i) {
            const int id = t + i * 512;
            const int r = id >> 3, a = id & 7;
            uint32_t hw[4], lw[4];
#pragma unroll
            for (int q = 0; q < 4; ++q) {
                const float x0 = va[i][2 * q], x1 = va[i][2 * q + 1];
                const __nv_bfloat162 hh = __floats2bfloat162_rn(x0, x1);
                const float l0 = x0 - __bfloat162float(hh.x);
                const float l1 = x1 - __bfloat162float(hh.y);
                const __nv_bfloat162 ll = __floats2bfloat162_rn(l0, l1);
                hw[q] = bf2bits(hh);
                lw[q] = bf2bits(ll);
            }
            const uint32_t swo = (uint32_t)(a * 16) ^ (uint32_t)((r & 7) << 4);
            const uint32_t d = sb + s * STAGE + r * 128 + swo;
            asm volatile("st.shared.v4.b32 [%0], {%1,%2,%3,%4};"
                         :: "r"(d), "r"(hw[0]), "r"(hw[1]), "r"(hw[2]), "r"(hw[3]) : "memory");
            asm volatile("st.shared.v4.b32 [%0], {%1,%2,%3,%4};"
                         :: "r"(d + 16384), "r"(lw[0]), "r"(lw[1]), "r"(lw[2]), "r"(lw[3]) : "memory");
        }
    };

    if (USENORM) { ldgA(0); issueB(0, 0); CP_COMMIT(); }
    else         { issueA(0, 0); issueB(0, 0); CP_COMMIT(); }

    for (int c = 0; c < CH; ++c) {
        const int s = c & 1;
        if (USENORM) {
            stsA(s);
            if (c + 1 < CH) { issueB(c + 1, s ^ 1); CP_COMMIT(); CP_WAIT(1); }
            else            { CP_WAIT(0); }
            __syncthreads();
            if (c + 1 < CH) ldgA(c + 1);
        } else {
            if (c + 1 < CH) {
                issueA(c + 1, s ^ 1);
                issueB(c + 1, s ^ 1);
                CP_COMMIT();
                CP_WAIT(1);
            } else {
                CP_WAIT(0);
            }
            __syncthreads();
        }

        const uint32_t aBh = sb + s * STAGE;
        const uint32_t aBl = aBh + 16384;
        const uint32_t bBh = aBh + 32768;
        const uint32_t bBl = bBh + BPLANE;

        const int rowL = lane & 15;
        const uint32_t xorA = (uint32_t)((rowL & 7) << 4);
        const uint32_t colA0 = (uint32_t)((lane >> 4) * 16);
        const int nl = ((lane >> 4) << 3) + (lane & 7);
        const uint32_t xorB = (uint32_t)((nl & 7) << 4);
        const uint32_t colB0 = (uint32_t)(((lane >> 3) & 1) * 16);

#pragma unroll
        for (int s16 = 0; s16 < 4; ++s16) {
#pragma unroll
            for (int mth = 0; mth < 2; ++mth) {       // mt pairs {0,1},{2,3}
                uint32_t afh[2][4], afl[2][4];
#pragma unroll
                for (int q = 0; q < 2; ++q) {
                    const int mt = mth * 2 + q;
                    const uint32_t off = (uint32_t)(warpM + mt * 16 + rowL) * 128 +
                                         ((colA0 + s16 * 32) ^ xorA);
                    ldsm4(afh[q][0], afh[q][1], afh[q][2], afh[q][3], aBh + off);
                    ldsm4(afl[q][0], afl[q][1], afl[q][2], afl[q][3], aBl + off);
                }
#pragma unroll
                for (int np = 0; np < NT / 2; ++np) {
                    const uint32_t offB = (uint32_t)(warpN + np * 16 + nl) * 128 +
                                          ((colB0 + s16 * 32) ^ xorB);
                    uint32_t bh0, bh1, bh2, bh3, bl0, bl1, bl2, bl3;
                    ldsm4(bh0, bh1, bh2, bh3, bBh + offB);
                    ldsm4(bl0, bl1, bl2, bl3, bBl + offB);
                    // spaced so each acc is revisited every ~4 MMAs
#pragma unroll
                    for (int q = 0; q < 2; ++q)
                        mma16816(acc[mth * 2 + q][2 * np], afh[q], bh0, bh1);
#pragma unroll
                    for (int q = 0; q < 2; ++q)
                        mma16816(acc[mth * 2 + q][2 * np + 1], afh[q], bh2, bh3);
#pragma unroll
                    for (int q = 0; q < 2; ++q)
                        mma16816(acc[mth * 2 + q][2 * np], afh[q], bl0, bl1);
#pragma unroll
                    for (int q = 0; q < 2; ++q)
                        mma16816(acc[mth * 2 + q][2 * np + 1], afh[q], bl2, bl3);
#pragma unroll
                    for (int q = 0; q < 2; ++q)
                        mma16816(acc[mth * 2 + q][2 * np], afl[q], bh0, bh1);
#pragma unroll
                    for (int q = 0; q < 2; ++q)
                        mma16816(acc[mth * 2 + q][2 * np + 1], afl[q], bh2, bh3);
                }
            }
        }
        __syncthreads();
    }

    // ---- epilogue: write C + per-column stats ----
    const int g = lane >> 2, tig = lane & 3;
#pragma unroll
    for (int mt = 0; mt < 4; ++mt) {
#pragma unroll
        for (int nt = 0; nt < NT; ++nt) {
            const int row = row0 + warpM + mt * 16 + g;
            const int col = warpN + nt * 8 + tig * 2;
            *(float2*)(C + (size_t)row * NOUT + col) =
                make_float2(acc[mt][nt][0], acc[mt][nt][1]);
            *(float2*)(C + (size_t)(row + 8) * NOUT + col) =
                make_float2(acc[mt][nt][2], acc[mt][nt][3]);
        }
    }
#pragma unroll
    for (int nt = 0; nt < NT; ++nt) {
        float s0 = 0.f, s1 = 0.f, q0 = 0.f, q1 = 0.f;
#pragma unroll
        for (int mt = 0; mt < 4; ++mt) {
            const float a0 = acc[mt][nt][0], a1 = acc[mt][nt][1];
            const float a2 = acc[mt][nt][2], a3 = acc[mt][nt][3];
            s0 += a0 + a2;  s1 += a1 + a3;
            q0 += a0 * a0 + a2 * a2;
            q1 += a1 * a1 + a3 * a3;
        }
#pragma unroll
        for (int o = 4; o < 32; o <<= 1) {
            s0 += __shfl_xor_sync(~0u, s0, o);
            s1 += __shfl_xor_sync(~0u, s1, o);
            q0 += __shfl_xor_sync(~0u, q0, o);
            q1 += __shfl_xor_sync(~0u, q1, o);
        }
        if (g == 0) {
            const int col = warpN + nt * 8 + tig * 2;
            atomicAdd(&sS[col], s0);  atomicAdd(&sS[col + 1], s1);
            atomicAdd(&sQ[col], q0);  atomicAdd(&sQ[col + 1], q1);
        }
    }
    __syncthreads();
    if (t < NOUT) {
        atomicAdd(statS + b * NOUT + t, sS[t]);
        atomicAdd(statQ + b * NOUT + t, sQ[t]);
        __threadfence();
    }
    __syncthreads();

    // ---- last block of this batch computes scale/shift for next stage ----
    __shared__ int sLast;
    if (t == 0) sLast = (atomicAdd(&counter[b], 1) == 63);
    __syncthreads();
    if (sLast && t < NOUT) {
        const float s = *(volatile float*)(statS + b * NOUT + t);
        const float q = *(volatile float*)(statQ + b * NOUT + t);
        float gs = s, gq = q;
#pragma unroll
        for (int o = CPG >> 1; o; o >>= 1) {
            gs += __shfl_xor_sync(~0u, gs, o);
            gq += __shfl_xor_sync(~0u, gq, o);
        }
        const float cnt = (float)N1 * (float)CPG;
        const float mean = gs / cnt;
        const float var  = gq / cnt - mean * mean;
        const float rstd = rsqrtf(var + 1e-5f);
        const float sc = rstd * gw[t];
        oScale[b * NOUT + t] = sc;
        oShift[b * NOUT + t] = gb[t] - mean * sc;
    }
}

// ---------------- knn + interpolate + concat; extra blocks do weight prep ---
__device__ __forceinline__ void pack8_split(const float* x, __nv_bfloat16* ph,
                                            __nv_bfloat16* pl)
{
    uint32_t hw[4], lw[4];
#pragma unroll
    for (int q = 0; q < 4; ++q) {
        const __nv_bfloat162 hh = __floats2bfloat162_rn(x[2 * q], x[2 * q + 1]);
        const float l0 = x[2 * q] - __bfloat162float(hh.x);
        const float l1 = x[2 * q + 1] - __bfloat162float(hh.y);
        const __nv_bfloat162 ll = __floats2bfloat162_rn(l0, l1);
        hw[q] = bf2bits(hh);
        lw[q] = bf2bits(ll);
    }
    *(uint4*)ph = make_uint4(hw[0], hw[1], hw[2], hw[3]);
    *(uint4*)pl = make_uint4(lw[0], lw[1], lw[2], lw[3]);
}

__global__ __launch_bounds__(256) void knn_interp_kernel(
    const float* __restrict__ xyz1, const float* __restrict__ xyz2,
    const float* __restrict__ points1, const float* __restrict__ points2,
    const float* __restrict__ w0src, const float* __restrict__ w1src)
{
    const int b = blockIdx.y;

    if (blockIdx.x == N1 / 256) {   // prep slice: split weights, zero accums
        const int t = threadIdx.x;
        for (int i = b * (H0 * CIN / BB) + t; i < (b + 1) * (H0 * CIN / BB); i += 256) {
            const float x = w0src[i];
            const __nv_bfloat16 h = __float2bfloat16(x);
            g_w0h[i] = h;
            g_w0l[i] = __float2bfloat16(x - __bfloat162float(h));
        }
        for (int i = b * (H1 * H0 / BB) + t; i < (b + 1) * (H1 * H0 / BB); i += 256) {
            const float x = w1src[i];
            const __nv_bfloat16 h = __float2bfloat16(x);
            g_w1h[i] = h;
            g_w1l[i] = __float2bfloat16(x - __bfloat162float(h));
        }
        if (b == 0) {
            for (int i = t; i < BB * H0; i += 256) { g_s0[i] = 0.f; g_q0[i] = 0.f; }
            for (int i = t; i < BB * H1; i += 256) { g_s1[i] = 0.f; g_q1[i] = 0.f; }
            if (t < BB) { g_cnt0[t] = 0; g_cnt1[t] = 0; }
        }
        return;
    }

    __shared__ float4 sp[M2];
    const float* x2 = xyz2 + (size_t)b * M2 * 3;
    for (int j = threadIdx.x; j < M2; j += 256) {
        float x = x2[j * 3 + 0], y = x2[j * 3 + 1], z = x2[j * 3 + 2];
        sp[j] = make_float4(x, y, z, x * x + y * y + z * z);
    }
    __syncthreads();

    const int n = blockIdx.x * 256 + threadIdx.x;
    const float* p1 = xyz1 + ((size_t)b * N1 + n) * 3;
    const float px = p1[0], py = p1[1], pz = p1[2];
    const float psq = px * px + py * py + pz * pz;

    float d0 = 1e30f, d1 = 1e30f, d2 = 1e30f;
    int i0 = 0, i1 = 0, i2 = 0;
#pragma unroll 4
    for (int j = 0; j < M2; ++j) {
        float4 q = sp[j];
        float tdot = fmaf(px, q.x, fmaf(py, q.y, pz * q.z));
        float d = psq + q.w - 2.0f * tdot;
        if (d < d2) {
            if (d < d1) {
                if (d < d0) { d2 = d1; i2 = i1; d1 = d0; i1 = i0; d0 = d; i0 = j; }
                else        { d2 = d1; i2 = i1; d1 = d;  i1 = j; }
            } else          { d2 = d;  i2 = j; }
        }
    }
    float w0 = 1.0f / (d0 + 1e-8f);
    float w1 = 1.0f / (d1 + 1e-8f);
    float w2 = 1.0f / (d2 + 1e-8f);
    const float inv = 1.0f / (w0 + w1 + w2);
    w0 *= inv; w1 *= inv; w2 *= inv;

    const size_t m = (size_t)b * N1 + n;
    __nv_bfloat16* fh = g_fh + m * CIN;
    __nv_bfloat16* fl = g_fl + m * CIN;
    const float* pp1 = points1 + m * C1;

    float buf[8];
#pragma unroll 4
    for (int c = 0; c < C1; c += 8) {
        const float4 u = *(const float4*)(pp1 + c);
        const float4 v = *(const float4*)(pp1 + c + 4);
        buf[0] = u.x; buf[1] = u.y; buf[2] = u.z; buf[3] = u.w;
        buf[4] = v.x; buf[5] = v.y; buf[6] = v.z; buf[7] = v.w;
        pack8_split(buf, fh + c, fl + c);
    }

    const float* r0 = points2 + ((size_t)b * M2 + i0) * C2;
    const float* r1 = points2 + ((size_t)b * M2 + i1) * C2;
    const float* r2 = points2 + ((size_t)b * M2 + i2) * C2;
#pragma unroll 4
    for (int c = 0; c < C2; c += 8) {
#pragma unroll
        for (int h = 0; h < 2; ++h) {
            const float4 a = *(const float4*)(r0 + c + h * 4);
            const float4 bb = *(const float4*)(r1 + c + h * 4);
            const float4 cc = *(const float4*)(r2 + c + h * 4);
            buf[h * 4 + 0] = w0 * a.x + w1 * bb.x + w2 * cc.x;
            buf[h * 4 + 1] = w0 * a.y + w1 * bb.y + w2 * cc.y;
            buf[h * 4 + 2] = w0 * a.z + w1 * bb.z + w2 * cc.z;
            buf[h * 4 + 3] = w0 * a.w + w1 * bb.w + w2 * cc.w;
        }
        pack8_split(buf, fh + C1 + c, fl + C1 + c);
    }
}

// ---------------- final GN1 + ReLU in-place on d_out ------------------------
__global__ __launch_bounds__(256) void apply_kernel(
    float* __restrict__ out,
    const float* __restrict__ scale, const float* __restrict__ shift)
{
    const size_t i = ((size_t)blockIdx.x * 256 + threadIdx.x) * 4;
    const int c = (int)(i & (H1 - 1));
    const int b = (int)(i >> 20);
    const int idx = b * H1 + c;
    float4 v = *(float4*)(out + i);
    v.x = fmaxf(0.f, fmaf(v.x, scale[idx + 0], shift[idx + 0]));
    v.y = fmaxf(0.f, fmaf(v.y, scale[idx + 1], shift[idx + 1]));
    v.z = fmaxf(0.f, fmaf(v.z, scale[idx + 2], shift[idx + 2]));
    v.w = fmaxf(0.f, fmaf(v.w, scale[idx + 3], shift[idx + 3]));
    *(float4*)(out + i) = v;
}

// ---------------- launcher ---------------------------------------------------
extern "C" void kernel_launch(void* const* d_in, const int* in_sizes, int n_in,
                              void* d_out, int out_size)
{
    const float* xyz1    = (const float*)d_in[0];
    const float* xyz2    = (const float*)d_in[1];
    const float* points1 = (const float*)d_in[2];
    const float* points2 = (const float*)d_in[3];
    const float* w0      = (const float*)d_in[4];
    const float* w1      = (const float*)d_in[5];
    const float* gn0w    = (const float*)d_in[6];
    const float* gn0b    = (const float*)d_in[7];
    const float* gn1w    = (const float*)d_in[8];
    const float* gn1b    = (const float*)d_in[9];
    float* out = (float*)d_out;

    __nv_bfloat16 *fh, *fl, *w0h, *w0l, *w1h, *w1l;
    float *h1, *sc0, *sh0, *sc1, *sh1, *s0, *q0, *s1, *q1;
    int *c0, *c1;
    cudaGetSymbolAddress((void**)&fh,  g_fh);
    cudaGetSymbolAddress((void**)&fl,  g_fl);
    cudaGetSymbolAddress((void**)&w0h, g_w0h);
    cudaGetSymbolAddress((void**)&w0l, g_w0l);
    cudaGetSymbolAddress((void**)&w1h, g_w1h);
    cudaGetSymbolAddress((void**)&w1l, g_w1l);
    cudaGetSymbolAddress((void**)&h1,  g_h1);
    cudaGetSymbolAddress((void**)&sc0, g_scale0);
    cudaGetSymbolAddress((void**)&sh0, g_shift0);
    cudaGetSymbolAddress((void**)&sc1, g_scale1);
    cudaGetSymbolAddress((void**)&sh1, g_shift1);
    cudaGetSymbolAddress((void**)&s0,  g_s0);
    cudaGetSymbolAddress((void**)&q0,  g_q0);
    cudaGetSymbolAddress((void**)&s1,  g_s1);
    cudaGetSymbolAddress((void**)&q1,  g_q1);
    cudaGetSymbolAddress((void**)&c0,  g_cnt0);
    cudaGetSymbolAddress((void**)&c1,  g_cnt1);

    const int SMEM1 = 2 * (32768 + 2 * H0 * 128) + 2 * H0 * 4;  // 198656
    const int SMEM2 = 2 * (32768 + 2 * H1 * 128) + 2 * H1 * 4;  // 132096
    cudaFuncSetAttribute(mma_gemm<CIN, H0, 0>,
                         cudaFuncAttributeMaxDynamicSharedMemorySize, SMEM1);
    cudaFuncSetAttribute(mma_gemm<H0, H1, 1>,
                         cudaFuncAttributeMaxDynamicSharedMemorySize, SMEM2);

    // 1) knn interp + concat (split planes); last x-block column does
    //    weight pre-split + stat/counter zeroing
    knn_interp_kernel<<<dim3(N1 / 256 + 1, BB), 256>>>(
        xyz1, xyz2, points1, points2, w0, w1);

    // 2) h1 = feat @ w0^T; fused GN0 stats; last block/batch -> scale0/shift0
    mma_gemm<CIN, H0, 0><<<NPTS / 128, 512, SMEM1>>>(
        fh, fl, nullptr, w0h, w0l, h1, nullptr, nullptr,
        s0, q0, gn0w, gn0b, sc0, sh0, c0);

    // 3) out = relu(gn0(h1)) @ w1^T; fused GN1 stats -> scale1/shift1
    mma_gemm<H0, H1, 1><<<NPTS / 128, 512, SMEM2>>>(
        nullptr, nullptr, h1, w1h, w1l, out, sc0, sh0,
        s1, q1, gn1w, gn1b, sc1, sh1, c1);

    // 4) GN1 + ReLU in-place
    apply_kernel<<<(NPTS * H1) / (256 * 4), 256>>>(out, sc1, sh1);
}

// round 6
// speedup vs baseline: 2.6798x; 1.2550x over previous
#include <cuda_runtime.h>
#include <cuda_fp16.h>
#include <cstdint>
#include <cstddef>

// Problem constants (fixed by setup_inputs)
#define BB    8
#define N1    8192
#define M2    2048
#define C1    128
#define C2    256
#define CIN   384
#define H0    256
#define H1    128
#define NPTS  (BB * N1)   // 65536

// ---------------- scratch (device globals; no allocations allowed) ----------
__device__ __align__(16) __half g_fh[(size_t)NPTS * CIN];   // feat fp16 (single plane)
__device__ __align__(16) __half g_w0h[H0 * CIN];            // w0 fp16 (single plane)
__device__ __align__(16) __half g_w1h[H1 * H0];             // w1 fp16 hi
__device__ __align__(16) __half g_w1l[H1 * H0];             // w1 fp16 lo residual
__device__ float g_h1[(size_t)NPTS * H0];
__device__ float g_scale0[BB * H0];
__device__ float g_shift0[BB * H0];
__device__ float g_scale1[BB * H1];
__device__ float g_shift1[BB * H1];
__device__ float g_s0[BB * H0];
__device__ float g_q0[BB * H0];
__device__ float g_s1[BB * H1];
__device__ float g_q1[BB * H1];
__device__ int   g_cnt0[BB];
__device__ int   g_cnt1[BB];

// ---------------- PTX helpers ------------------------------------------------
__device__ __forceinline__ uint32_t smem_u32(const void* p) {
    uint32_t a;
    asm("{ .reg .u64 t; cvta.to.shared.u64 t, %1; cvt.u32.u64 %0, t; }"
        : "=r"(a) : "l"(p));
    return a;
}
__device__ __forceinline__ void cpa16(uint32_t dst, const void* src) {
    asm volatile("cp.async.cg.shared.global [%0], [%1], 16;"
                 :: "r"(dst), "l"(src) : "memory");
}
#define CP_COMMIT() asm volatile("cp.async.commit_group;" ::: "memory")
#define CP_WAIT(n)  asm volatile("cp.async.wait_group %0;" :: "n"(n) : "memory")

__device__ __forceinline__ void ldsm4(uint32_t& r0, uint32_t& r1,
                                      uint32_t& r2, uint32_t& r3, uint32_t a) {
    asm volatile("ldmatrix.sync.aligned.m8n8.x4.shared.b16 {%0,%1,%2,%3}, [%4];"
                 : "=r"(r0), "=r"(r1), "=r"(r2), "=r"(r3) : "r"(a));
}
__device__ __forceinline__ void mma16816(float* c, const uint32_t* a,
                                         uint32_t b0, uint32_t b1) {
    asm volatile(
        "mma.sync.aligned.m16n8k16.row.col.f32.f16.f16.f32 "
        "{%0,%1,%2,%3}, {%4,%5,%6,%7}, {%8,%9}, {%0,%1,%2,%3};"
        : "+f"(c[0]), "+f"(c[1]), "+f"(c[2]), "+f"(c[3])
        : "r"(a[0]), "r"(a[1]), "r"(a[2]), "r"(a[3]), "r"(b0), "r"(b1));
}
__device__ __forceinline__ uint32_t h2bits(__half2 v) {
    return *reinterpret_cast<uint32_t*>(&v);
}

// ---------------- fp16 GEMM on mma.sync + fused GN stats + fused scale ------
// C[m,n] = sum_k A'[m,k] * W[n,k]; block tile 128 x NOUT, 512 threads.
// MODE 0: A fp16 single plane via cp.async, B fp16 single plane -> 1 MMA/k16.
// MODE 1: A fp32 + GN fold + relu at load, split-2 fp16 in regs; B split-2
//         fp16 planes -> 3 MMA/k16 (exact to ~1e-7).
// Epilogue: per-(batch,channel) sum/sumsq; last block per batch folds stats
// into scale/shift for the next stage.
template <int K, int NOUT, int MODE>
__global__ __launch_bounds__(512, 1) void mma_gemm(
    const __half* __restrict__ Ah, const float* __restrict__ Af,
    const __half* __restrict__ Bh, const __half* __restrict__ Bl,
    float* __restrict__ C,
    const float* __restrict__ scale, const float* __restrict__ shift,
    float* __restrict__ statS, float* __restrict__ statQ,
    const float* __restrict__ gw, const float* __restrict__ gb,
    float* __restrict__ oScale, float* __restrict__ oShift,
    int* __restrict__ counter)
{
    constexpr int CH = K / 64;
    constexpr int WN = NOUT / 8;          // columns per warp
    constexpr int NT = WN / 8;            // n8-tiles per warp
    constexpr int APL = (MODE == 0) ? 1 : 2;
    constexpr int BPL = (MODE == 0) ? 1 : 2;
    constexpr int APLANE = 16384;         // 128 rows x 128B
    constexpr int BPLANE = NOUT * 128;
    constexpr int STAGE = APL * APLANE + BPL * BPLANE;
    constexpr int BITER = NOUT / 64;      // B atoms loop (512 thr, 1 atom each)
    constexpr int CPG = NOUT / 32;

    extern __shared__ __align__(128) char smem[];
    const uint32_t sb = smem_u32(smem);
    float* sS = (float*)(smem + 2 * STAGE);
    float* sQ = sS + NOUT;
    const int t = threadIdx.x;
    const int wid = t >> 5, lane = t & 31;
    const int warpM = (wid >> 3) * 64;
    const int warpN = (wid & 7) * WN;
    const int row0 = blockIdx.x * 128;
    const int b = row0 >> 13;

    if (t < NOUT) { sS[t] = 0.f; sQ[t] = 0.f; }

    float acc[4][NT][4];
#pragma unroll
    for (int i = 0; i < 4; ++i)
#pragma unroll
        for (int j = 0; j < NT; ++j)
#pragma unroll
            for (int q = 0; q < 4; ++q) acc[i][j][q] = 0.f;

    float va[2][8];   // MODE 1 staging

    auto issueB = [&](int c, int s) {
#pragma unroll
        for (int i = 0; i < BITER; ++i) {
            const int id = t + i * 512;
            const int n = id >> 3, a = id & 7;
            const uint32_t swo = (uint32_t)(a * 16) ^ (uint32_t)((n & 7) << 4);
            const uint32_t d = sb + s * STAGE + APL * APLANE + n * 128 + swo;
            const size_t src = (size_t)n * K + c * 64 + a * 8;
            cpa16(d, Bh + src);
            if (BPL == 2) cpa16(d + BPLANE, Bl + src);
        }
    };
    auto issueA = [&](int c, int s) {     // MODE 0
#pragma unroll
        for (int i = 0; i < 2; ++i) {
            const int id = t + i * 512;
            const int r = id >> 3, a = id & 7;
            const uint32_t swo = (uint32_t)(a * 16) ^ (uint32_t)((r & 7) << 4);
            const uint32_t d = sb + s * STAGE + r * 128 + swo;
            cpa16(d, Ah + (size_t)(row0 + r) * K + c * 64 + a * 8);
        }
    };
    auto ldgA = [&](int c) {              // MODE 1
#pragma unroll
        for (int i = 0; i < 2; ++i) {
            const int id = t + i * 512;
            const int r = id >> 3, a = id & 7;
            const float* p = Af + (size_t)(row0 + r) * K + c * 64 + a * 8;
            const float4 u = *(const float4*)p;
            const float4 v = *(const float4*)(p + 4);
            const int col = b * K + c * 64 + a * 8;
            const float4 s0 = *(const float4*)(scale + col);
            const float4 s1 = *(const float4*)(scale + col + 4);
            const float4 h0 = *(const float4*)(shift + col);
            const float4 h1 = *(const float4*)(shift + col + 4);
            va[i][0] = fmaxf(0.f, fmaf(u.x, s0.x, h0.x));
            va[i][1] = fmaxf(0.f, fmaf(u.y, s0.y, h0.y));
            va[i][2] = fmaxf(0.f, fmaf(u.z, s0.z, h0.z));
            va[i][3] = fmaxf(0.f, fmaf(u.w, s0.w, h0.w));
            va[i][4] = fmaxf(0.f, fmaf(v.x, s1.x, h1.x));
            va[i][5] = fmaxf(0.f, fmaf(v.y, s1.y, h1.y));
            va[i][6] = fmaxf(0.f, fmaf(v.z, s1.z, h1.z));
            va[i][7] = fmaxf(0.f, fmaf(v.w, s1.w, h1.w));
        }
    };
    auto stsA = [&](int s) {              // MODE 1: split-2 fp16 store
#pragma unroll
        for (int i = 0; i < 2; ++i) {
            const int id = t + i * 512;
            const int r = id >> 3, a = id & 7;
            uint32_t hw[4], lw[4];
#pragma unroll
            for (int q = 0; q < 4; ++q) {
                const float x0 = va[i][2 * q], x1 = va[i][2 * q + 1];
                const __half2 hh = __floats2half2_rn(x0, x1);
                const float l0 = x0 - __half2float(__low2half(hh));
                const float l1 = x1 - __half2float(__high2half(hh));
                hw[q] = h2bits(hh);
                lw[q] = h2bits(__floats2half2_rn(l0, l1));
            }
            const uint32_t swo = (uint32_t)(a * 16) ^ (uint32_t)((r & 7) << 4);
            const uint32_t d = sb + s * STAGE + r * 128 + swo;
            asm volatile("st.shared.v4.b32 [%0], {%1,%2,%3,%4};"
                         :: "r"(d), "r"(hw[0]), "r"(hw[1]), "r"(hw[2]), "r"(hw[3]) : "memory");
            asm volatile("st.shared.v4.b32 [%0], {%1,%2,%3,%4};"
                         :: "r"(d + APLANE), "r"(lw[0]), "r"(lw[1]), "r"(lw[2]), "r"(lw[3]) : "memory");
        }
    };

    if (MODE == 1) { ldgA(0); issueB(0, 0); CP_COMMIT(); }
    else           { issueA(0, 0); issueB(0, 0); CP_COMMIT(); }

    for (int c = 0; c < CH; ++c) {
        const int s = c & 1;
        if (MODE == 1) {
            stsA(s);
            if (c + 1 < CH) { issueB(c + 1, s ^ 1); CP_COMMIT(); CP_WAIT(1); }
            else            { CP_WAIT(0); }
            __syncthreads();
            if (c + 1 < CH) ldgA(c + 1);
        } else {
            if (c + 1 < CH) {
                issueA(c + 1, s ^ 1);
                issueB(c + 1, s ^ 1);
                CP_COMMIT();
                CP_WAIT(1);
            } else {
                CP_WAIT(0);
            }
            __syncthreads();
        }

        const uint32_t aBh = sb + s * STAGE;
        const uint32_t aBl = aBh + APLANE;
        const uint32_t bBh = sb + s * STAGE + APL * APLANE;
        const uint32_t bBl = bBh + BPLANE;

        const int rowL = lane & 15;
        const uint32_t xorA = (uint32_t)((rowL & 7) << 4);
        const uint32_t colA0 = (uint32_t)((lane >> 4) * 16);
        const int nl = ((lane >> 4) << 3) + (lane & 7);
        const uint32_t xorB = (uint32_t)((nl & 7) << 4);
        const uint32_t colB0 = (uint32_t)(((lane >> 3) & 1) * 16);

#pragma unroll
        for (int s16 = 0; s16 < 4; ++s16) {
#pragma unroll
            for (int mth = 0; mth < 2; ++mth) {
                uint32_t afh[2][4], afl[2][4];
#pragma unroll
                for (int q = 0; q < 2; ++q) {
                    const int mt = mth * 2 + q;
                    const uint32_t off = (uint32_t)(warpM + mt * 16 + rowL) * 128 +
                                         ((colA0 + s16 * 32) ^ xorA);
                    ldsm4(afh[q][0], afh[q][1], afh[q][2], afh[q][3], aBh + off);
                    if (MODE == 1)
                        ldsm4(afl[q][0], afl[q][1], afl[q][2], afl[q][3], aBl + off);
                }
#pragma unroll
                for (int np = 0; np < NT / 2; ++np) {
                    const uint32_t offB = (uint32_t)(warpN + np * 16 + nl) * 128 +
                                          ((colB0 + s16 * 32) ^ xorB);
                    uint32_t bh0, bh1, bh2, bh3;
                    ldsm4(bh0, bh1, bh2, bh3, bBh + offB);
                    if (MODE == 0) {
#pragma unroll
                        for (int q = 0; q < 2; ++q)
                            mma16816(acc[mth * 2 + q][2 * np], afh[q], bh0, bh1);
#pragma unroll
                        for (int q = 0; q < 2; ++q)
                            mma16816(acc[mth * 2 + q][2 * np + 1], afh[q], bh2, bh3);
                    } else {
                        uint32_t bl0, bl1, bl2, bl3;
                        ldsm4(bl0, bl1, bl2, bl3, bBl + offB);
#pragma unroll
                        for (int q = 0; q < 2; ++q)
                            mma16816(acc[mth * 2 + q][2 * np], afh[q], bh0, bh1);
#pragma unroll
                        for (int q = 0; q < 2; ++q)
                            mma16816(acc[mth * 2 + q][2 * np + 1], afh[q], bh2, bh3);
#pragma unroll
                        for (int q = 0; q < 2; ++q)
                            mma16816(acc[mth * 2 + q][2 * np], afh[q], bl0, bl1);
#pragma unroll
                        for (int q = 0; q < 2; ++q)
                            mma16816(acc[mth * 2 + q][2 * np + 1], afh[q], bl2, bl3);
#pragma unroll
                        for (int q = 0; q < 2; ++q)
                            mma16816(acc[mth * 2 + q][2 * np], afl[q], bh0, bh1);
#pragma unroll
                        for (int q = 0; q < 2; ++q)
                            mma16816(acc[mth * 2 + q][2 * np + 1], afl[q], bh2, bh3);
                    }
                }
            }
        }
        __syncthreads();
    }

    // ---- epilogue: write C + per-column stats ----
    const int g = lane >> 2, tig = lane & 3;
#pragma unroll
    for (int mt = 0; mt < 4; ++mt) {
#pragma unroll
        for (int nt = 0; nt < NT; ++nt) {
            const int row = row0 + warpM + mt * 16 + g;
            const int col = warpN + nt * 8 + tig * 2;
            *(float2*)(C + (size_t)row * NOUT + col) =
                make_float2(acc[mt][nt][0], acc[mt][nt][1]);
            *(float2*)(C + (size_t)(row + 8) * NOUT + col) =
                make_float2(acc[mt][nt][2], acc[mt][nt][3]);
        }
    }
#pragma unroll
    for (int nt = 0; nt < NT; ++nt) {
        float s0 = 0.f, s1 = 0.f, q0 = 0.f, q1 = 0.f;
#pragma unroll
        for (int mt = 0; mt < 4; ++mt) {
            const float a0 = acc[mt][nt][0], a1 = acc[mt][nt][1];
            const float a2 = acc[mt][nt][2], a3 = acc[mt][nt][3];
            s0 += a0 + a2;  s1 += a1 + a3;
            q0 += a0 * a0 + a2 * a2;
            q1 += a1 * a1 + a3 * a3;
        }
#pragma unroll
        for (int o = 4; o < 32; o <<= 1) {
            s0 += __shfl_xor_sync(~0u, s0, o);
            s1 += __shfl_xor_sync(~0u, s1, o);
            q0 += __shfl_xor_sync(~0u, q0, o);
            q1 += __shfl_xor_sync(~0u, q1, o);
        }
        if (g == 0) {
            const int col = warpN + nt * 8 + tig * 2;
            atomicAdd(&sS[col], s0);  atomicAdd(&sS[col + 1], s1);
            atomicAdd(&sQ[col], q0);  atomicAdd(&sQ[col + 1], q1);
        }
    }
    __syncthreads();
    if (t < NOUT) {
        atomicAdd(statS + b * NOUT + t, sS[t]);
        atomicAdd(statQ + b * NOUT + t, sQ[t]);
        __threadfence();
    }
    __syncthreads();

    __shared__ int sLast;
    if (t == 0) sLast = (atomicAdd(&counter[b], 1) == 63);
    __syncthreads();
    if (sLast && t < NOUT) {
        const float s = *(volatile float*)(statS + b * NOUT + t);
        const float q = *(volatile float*)(statQ + b * NOUT + t);
        float gs = s, gq = q;
#pragma unroll
        for (int o = CPG >> 1; o; o >>= 1) {
            gs += __shfl_xor_sync(~0u, gs, o);
            gq += __shfl_xor_sync(~0u, gq, o);
        }
        const float cnt = (float)N1 * (float)CPG;
        const float mean = gs / cnt;
        const float var  = gq / cnt - mean * mean;
        const float rstd = rsqrtf(var + 1e-5f);
        const float sc = rstd * gw[t];
        oScale[b * NOUT + t] = sc;
        oShift[b * NOUT + t] = gb[t] - mean * sc;
    }
}

// ---------------- knn + interpolate + concat; extra blocks do weight prep ---
__device__ __forceinline__ void pack8_h(const float* x, __half* p)
{
    uint32_t w[4];
#pragma unroll
    for (int q = 0; q < 4; ++q)
        w[q] = h2bits(__floats2half2_rn(x[2 * q], x[2 * q + 1]));
    *(uint4*)p = make_uint4(w[0], w[1], w[2], w[3]);
}

__global__ __launch_bounds__(256) void knn_interp_kernel(
    const float* __restrict__ xyz1, const float* __restrict__ xyz2,
    const float* __restrict__ points1, const float* __restrict__ points2,
    const float* __restrict__ w0src, const float* __restrict__ w1src)
{
    const int b = blockIdx.y;

    if (blockIdx.x == N1 / 256) {   // prep slice: weights + zero accums
        const int t = threadIdx.x;
        for (int i = b * (H0 * CIN / BB) + t; i < (b + 1) * (H0 * CIN / BB); i += 256)
            g_w0h[i] = __float2half_rn(w0src[i]);
        for (int i = b * (H1 * H0 / BB) + t; i < (b + 1) * (H1 * H0 / BB); i += 256) {
            const float x = w1src[i];
            const __half h = __float2half_rn(x);
            g_w1h[i] = h;
            g_w1l[i] = __float2half_rn(x - __half2float(h));
        }
        if (b == 0) {
            for (int i = t; i < BB * H0; i += 256) { g_s0[i] = 0.f; g_q0[i] = 0.f; }
            for (int i = t; i < BB * H1; i += 256) { g_s1[i] = 0.f; g_q1[i] = 0.f; }
            if (t < BB) { g_cnt0[t] = 0; g_cnt1[t] = 0; }
        }
        return;
    }

    __shared__ float4 sp[M2];
    const float* x2 = xyz2 + (size_t)b * M2 * 3;
    for (int j = threadIdx.x; j < M2; j += 256) {
        float x = x2[j * 3 + 0], y = x2[j * 3 + 1], z = x2[j * 3 + 2];
        sp[j] = make_float4(x, y, z, x * x + y * y + z * z);
    }
    __syncthreads();

    const int n = blockIdx.x * 256 + threadIdx.x;
    const float* p1 = xyz1 + ((size_t)b * N1 + n) * 3;
    const float px = p1[0], py = p1[1], pz = p1[2];
    const float psq = px * px + py * py + pz * pz;

    float d0 = 1e30f, d1 = 1e30f, d2 = 1e30f;
    int i0 = 0, i1 = 0, i2 = 0;
#pragma unroll 4
    for (int j = 0; j < M2; ++j) {
        float4 q = sp[j];
        float tdot = fmaf(px, q.x, fmaf(py, q.y, pz * q.z));
        float d = psq + q.w - 2.0f * tdot;
        if (d < d2) {
            if (d < d1) {
                if (d < d0) { d2 = d1; i2 = i1; d1 = d0; i1 = i0; d0 = d; i0 = j; }
                else        { d2 = d1; i2 = i1; d1 = d;  i1 = j; }
            } else          { d2 = d;  i2 = j; }
        }
    }
    float w0 = 1.0f / (d0 + 1e-8f);
    float w1 = 1.0f / (d1 + 1e-8f);
    float w2 = 1.0f / (d2 + 1e-8f);
    const float inv = 1.0f / (w0 + w1 + w2);
    w0 *= inv; w1 *= inv; w2 *= inv;

    const size_t m = (size_t)b * N1 + n;
    __half* fh = g_fh + m * CIN;
    const float* pp1 = points1 + m * C1;

    float buf[8];
#pragma unroll 4
    for (int c = 0; c < C1; c += 8) {
        const float4 u = *(const float4*)(pp1 + c);
        const float4 v = *(const float4*)(pp1 + c + 4);
        buf[0] = u.x; buf[1] = u.y; buf[2] = u.z; buf[3] = u.w;
        buf[4] = v.x; buf[5] = v.y; buf[6] = v.z; buf[7] = v.w;
        pack8_h(buf, fh + c);
    }

    const float* r0 = points2 + ((size_t)b * M2 + i0) * C2;
    const float* r1 = points2 + ((size_t)b * M2 + i1) * C2;
    const float* r2 = points2 + ((size_t)b * M2 + i2) * C2;
#pragma unroll 4
    for (int c = 0; c < C2; c += 8) {
#pragma unroll
        for (int h = 0; h < 2; ++h) {
            const float4 a = *(const float4*)(r0 + c + h * 4);
            const float4 bb = *(const float4*)(r1 + c + h * 4);
            const float4 cc = *(const float4*)(r2 + c + h * 4);
            buf[h * 4 + 0] = w0 * a.x + w1 * bb.x + w2 * cc.x;
            buf[h * 4 + 1] = w0 * a.y + w1 * bb.y + w2 * cc.y;
            buf[h * 4 + 2] = w0 * a.z + w1 * bb.z + w2 * cc.z;
            buf[h * 4 + 3] = w0 * a.w + w1 * bb.w + w2 * cc.w;
        }
        pack8_h(buf, fh + C1 + c);
    }
}

// ---------------- final GN1 + ReLU in-place on d_out ------------------------
__global__ __launch_bounds__(256) void apply_kernel(
    float* __restrict__ out,
    const float* __restrict__ scale, const float* __restrict__ shift)
{
    const size_t i = ((size_t)blockIdx.x * 256 + threadIdx.x) * 4;
    const int c = (int)(i & (H1 - 1));
    const int b = (int)(i >> 20);
    const int idx = b * H1 + c;
    float4 v = *(float4*)(out + i);
    v.x = fmaxf(0.f, fmaf(v.x, scale[idx + 0], shift[idx + 0]));
    v.y = fmaxf(0.f, fmaf(v.y, scale[idx + 1], shift[idx + 1]));
    v.z = fmaxf(0.f, fmaf(v.z, scale[idx + 2], shift[idx + 2]));
    v.w = fmaxf(0.f, fmaf(v.w, scale[idx + 3], shift[idx + 3]));
    *(float4*)(out + i) = v;
}

// ---------------- launcher ---------------------------------------------------
extern "C" void kernel_launch(void* const* d_in, const int* in_sizes, int n_in,
                              void* d_out, int out_size)
{
    const float* xyz1    = (const float*)d_in[0];
    const float* xyz2    = (const float*)d_in[1];
    const float* points1 = (const float*)d_in[2];
    const float* points2 = (const float*)d_in[3];
    const float* w0      = (const float*)d_in[4];
    const float* w1      = (const float*)d_in[5];
    const float* gn0w    = (const float*)d_in[6];
    const float* gn0b    = (const float*)d_in[7];
    const float* gn1w    = (const float*)d_in[8];
    const float* gn1b    = (const float*)d_in[9];
    float* out = (float*)d_out;

    __half *fh, *w0h, *w1h, *w1l;
    float *h1, *sc0, *sh0, *sc1, *sh1, *s0, *q0, *s1, *q1;
    int *c0, *c1;
    cudaGetSymbolAddress((void**)&fh,  g_fh);
    cudaGetSymbolAddress((void**)&w0h, g_w0h);
    cudaGetSymbolAddress((void**)&w1h, g_w1h);
    cudaGetSymbolAddress((void**)&w1l, g_w1l);
    cudaGetSymbolAddress((void**)&h1,  g_h1);
    cudaGetSymbolAddress((void**)&sc0, g_scale0);
    cudaGetSymbolAddress((void**)&sh0, g_shift0);
    cudaGetSymbolAddress((void**)&sc1, g_scale1);
    cudaGetSymbolAddress((void**)&sh1, g_shift1);
    cudaGetSymbolAddress((void**)&s0,  g_s0);
    cudaGetSymbolAddress((void**)&q0,  g_q0);
    cudaGetSymbolAddress((void**)&s1,  g_s1);
    cudaGetSymbolAddress((void**)&q1,  g_q1);
    cudaGetSymbolAddress((void**)&c0,  g_cnt0);
    cudaGetSymbolAddress((void**)&c1,  g_cnt1);

    // GEMM1 (MODE 0): stage = A 16KB + B 32KB; GEMM2 (MODE 1): 32KB + 32KB
    const int SMEM1 = 2 * (16384 + H0 * 128) + 2 * H0 * 4;       // 100352
    const int SMEM2 = 2 * (2 * 16384 + 2 * H1 * 128) + 2 * H1 * 4;  // 132096
    cudaFuncSetAttribute(mma_gemm<CIN, H0, 0>,
                         cudaFuncAttributeMaxDynamicSharedMemorySize, SMEM1);
    cudaFuncSetAttribute(mma_gemm<H0, H1, 1>,
                         cudaFuncAttributeMaxDynamicSharedMemorySize, SMEM2);

    // 1) knn interp + concat (fp16 plane); last x-column does weight prep
    knn_interp_kernel<<<dim3(N1 / 256 + 1, BB), 256>>>(
        xyz1, xyz2, points1, points2, w0, w1);

    // 2) h1 = feat @ w0^T (single-plane fp16, 1 MMA/k16); fused GN0 stats
    mma_gemm<CIN, H0, 0><<<NPTS / 128, 512, SMEM1>>>(
        fh, nullptr, w0h, nullptr, h1, nullptr, nullptr,
        s0, q0, gn0w, gn0b, sc0, sh0, c0);

    // 3) out = relu(gn0(h1)) @ w1^T (split-2 fp16, 3 MMA/k16); fused GN1 stats
    mma_gemm<H0, H1, 1><<<NPTS / 128, 512, SMEM2>>>(
        nullptr, h1, w1h, w1l, out, sc0, sh0,
        s1, q1, gn1w, gn1b, sc1, sh1, c1);

    // 4) GN1 + ReLU in-place
    apply_kernel<<<(NPTS * H1) / (256 * 4), 256>>>(out, sc1, sh1);
}

// round 7
// speedup vs baseline: 2.9593x; 1.1043x over previous
#include <cuda_runtime.h>
#include <cuda_fp16.h>
#include <cstdint>
#include <cstddef>

// Problem constants (fixed by setup_inputs)
#define BB    8
#define N1    8192
#define M2    2048
#define C1    128
#define C2    256
#define CIN   384
#define H0    256
#define H1    128
#define NPTS  (BB * N1)   // 65536

// ---------------- scratch (device globals; no allocations allowed) ----------
__device__ __align__(16) __half g_fh[(size_t)NPTS * CIN];   // feat fp16
__device__ __align__(16) __half g_w0h[H0 * CIN];            // w0 fp16
__device__ __align__(16) __half g_w1h[H1 * H0];             // w1 fp16
__device__ float g_h1[(size_t)NPTS * H0];
__device__ float g_scale0[BB * H0];
__device__ float g_shift0[BB * H0];
__device__ float g_scale1[BB * H1];
__device__ float g_shift1[BB * H1];
__device__ float g_s0[BB * H0];
__device__ float g_q0[BB * H0];
__device__ float g_s1[BB * H1];
__device__ float g_q1[BB * H1];
__device__ int   g_cnt0[BB];
__device__ int   g_cnt1[BB];

// ---------------- PTX helpers ------------------------------------------------
__device__ __forceinline__ uint32_t smem_u32(const void* p) {
    uint32_t a;
    asm("{ .reg .u64 t; cvta.to.shared.u64 t, %1; cvt.u32.u64 %0, t; }"
        : "=r"(a) : "l"(p));
    return a;
}
__device__ __forceinline__ void cpa16(uint32_t dst, const void* src) {
    asm volatile("cp.async.cg.shared.global [%0], [%1], 16;"
                 :: "r"(dst), "l"(src) : "memory");
}
#define CP_COMMIT() asm volatile("cp.async.commit_group;" ::: "memory")
#define CP_WAIT(n)  asm volatile("cp.async.wait_group %0;" :: "n"(n) : "memory")

__device__ __forceinline__ void ldsm4(uint32_t& r0, uint32_t& r1,
                                      uint32_t& r2, uint32_t& r3, uint32_t a) {
    asm volatile("ldmatrix.sync.aligned.m8n8.x4.shared.b16 {%0,%1,%2,%3}, [%4];"
                 : "=r"(r0), "=r"(r1), "=r"(r2), "=r"(r3) : "r"(a));
}
__device__ __forceinline__ void mma16816(float* c, const uint32_t* a,
                                         uint32_t b0, uint32_t b1) {
    asm volatile(
        "mma.sync.aligned.m16n8k16.row.col.f32.f16.f16.f32 "
        "{%0,%1,%2,%3}, {%4,%5,%6,%7}, {%8,%9}, {%0,%1,%2,%3};"
        : "+f"(c[0]), "+f"(c[1]), "+f"(c[2]), "+f"(c[3])
        : "r"(a[0]), "r"(a[1]), "r"(a[2]), "r"(a[3]), "r"(b0), "r"(b1));
}
__device__ __forceinline__ uint32_t h2bits(__half2 v) {
    return *reinterpret_cast<uint32_t*>(&v);
}

// ---------------- fp16 GEMM on mma.sync + fused GN stats + fused scale ------
// C[m,n] = sum_k A'[m,k] * W[n,k]; block tile 128 x NOUT, 512 threads.
// Single fp16 plane for A and B -> 1 MMA per k16.
// MODE 0: A fp16 via cp.async. MODE 1: A fp32 + GN fold + relu at load,
// converted to fp16 in regs, stored to smem.
// Epilogue: per-(batch,channel) sum/sumsq; last block per batch folds stats
// into scale/shift for the next stage.
template <int K, int NOUT, int MODE>
__global__ __launch_bounds__(512, 1) void mma_gemm(
    const __half* __restrict__ Ah, const float* __restrict__ Af,
    const __half* __restrict__ Bh,
    float* __restrict__ C,
    const float* __restrict__ scale, const float* __restrict__ shift,
    float* __restrict__ statS, float* __restrict__ statQ,
    const float* __restrict__ gw, const float* __restrict__ gb,
    float* __restrict__ oScale, float* __restrict__ oShift,
    int* __restrict__ counter)
{
    constexpr int CH = K / 64;
    constexpr int WN = NOUT / 8;          // columns per warp
    constexpr int NT = WN / 8;            // n8-tiles per warp
    constexpr int APLANE = 16384;         // 128 rows x 128B
    constexpr int BPLANE = NOUT * 128;
    constexpr int STAGE = APLANE + BPLANE;
    constexpr int BITER = NOUT / 64;
    constexpr int CPG = NOUT / 32;

    extern __shared__ __align__(128) char smem[];
    const uint32_t sb = smem_u32(smem);
    float* sS = (float*)(smem + 2 * STAGE);
    float* sQ = sS + NOUT;
    const int t = threadIdx.x;
    const int wid = t >> 5, lane = t & 31;
    const int warpM = (wid >> 3) * 64;
    const int warpN = (wid & 7) * WN;
    const int row0 = blockIdx.x * 128;
    const int b = row0 >> 13;

    if (t < NOUT) { sS[t] = 0.f; sQ[t] = 0.f; }

    float acc[4][NT][4];
#pragma unroll
    for (int i = 0; i < 4; ++i)
#pragma unroll
        for (int j = 0; j < NT; ++j)
#pragma unroll
            for (int q = 0; q < 4; ++q) acc[i][j][q] = 0.f;

    float va[2][8];   // MODE 1 staging

    auto issueB = [&](int c, int s) {
#pragma unroll
        for (int i = 0; i < BITER; ++i) {
            const int id = t + i * 512;
            const int n = id >> 3, a = id & 7;
            const uint32_t swo = (uint32_t)(a * 16) ^ (uint32_t)((n & 7) << 4);
            cpa16(sb + s * STAGE + APLANE + n * 128 + swo,
                  Bh + (size_t)n * K + c * 64 + a * 8);
        }
    };
    auto issueA = [&](int c, int s) {     // MODE 0
#pragma unroll
        for (int i = 0; i < 2; ++i) {
            const int id = t + i * 512;
            const int r = id >> 3, a = id & 7;
            const uint32_t swo = (uint32_t)(a * 16) ^ (uint32_t)((r & 7) << 4);
            cpa16(sb + s * STAGE + r * 128 + swo,
                  Ah + (size_t)(row0 + r) * K + c * 64 + a * 8);
        }
    };
    auto ldgA = [&](int c) {              // MODE 1
#pragma unroll
        for (int i = 0; i < 2; ++i) {
            const int id = t + i * 512;
            const int r = id >> 3, a = id & 7;
            const float* p = Af + (size_t)(row0 + r) * K + c * 64 + a * 8;
            const float4 u = *(const float4*)p;
            const float4 v = *(const float4*)(p + 4);
            const int col = b * K + c * 64 + a * 8;
            const float4 s0 = *(const float4*)(scale + col);
            const float4 s1 = *(const float4*)(scale + col + 4);
            const float4 h0 = *(const float4*)(shift + col);
            const float4 h1 = *(const float4*)(shift + col + 4);
            va[i][0] = fmaxf(0.f, fmaf(u.x, s0.x, h0.x));
            va[i][1] = fmaxf(0.f, fmaf(u.y, s0.y, h0.y));
            va[i][2] = fmaxf(0.f, fmaf(u.z, s0.z, h0.z));
            va[i][3] = fmaxf(0.f, fmaf(u.w, s0.w, h0.w));
            va[i][4] = fmaxf(0.f, fmaf(v.x, s1.x, h1.x));
            va[i][5] = fmaxf(0.f, fmaf(v.y, s1.y, h1.y));
            va[i][6] = fmaxf(0.f, fmaf(v.z, s1.z, h1.z));
            va[i][7] = fmaxf(0.f, fmaf(v.w, s1.w, h1.w));
        }
    };
    auto stsA = [&](int s) {              // MODE 1: fp16 convert + store
#pragma unroll
        for (int i = 0; i < 2; ++i) {
            const int id = t + i * 512;
            const int r = id >> 3, a = id & 7;
            uint32_t hw[4];
#pragma unroll
            for (int q = 0; q < 4; ++q)
                hw[q] = h2bits(__floats2half2_rn(va[i][2 * q], va[i][2 * q + 1]));
            const uint32_t swo = (uint32_t)(a * 16) ^ (uint32_t)((r & 7) << 4);
            asm volatile("st.shared.v4.b32 [%0], {%1,%2,%3,%4};"
                         :: "r"(sb + s * STAGE + r * 128 + swo),
                            "r"(hw[0]), "r"(hw[1]), "r"(hw[2]), "r"(hw[3]) : "memory");
        }
    };

    if (MODE == 1) { ldgA(0); issueB(0, 0); CP_COMMIT(); }
    else           { issueA(0, 0); issueB(0, 0); CP_COMMIT(); }

    for (int c = 0; c < CH; ++c) {
        const int s = c & 1;
        if (MODE == 1) {
            stsA(s);
            if (c + 1 < CH) { issueB(c + 1, s ^ 1); CP_COMMIT(); CP_WAIT(1); }
            else            { CP_WAIT(0); }
            __syncthreads();
            if (c + 1 < CH) ldgA(c + 1);
        } else {
            if (c + 1 < CH) {
                issueA(c + 1, s ^ 1);
                issueB(c + 1, s ^ 1);
                CP_COMMIT();
                CP_WAIT(1);
            } else {
                CP_WAIT(0);
            }
            __syncthreads();
        }

        const uint32_t aB = sb + s * STAGE;
        const uint32_t bB = aB + APLANE;

        const int rowL = lane & 15;
        const uint32_t xorA = (uint32_t)((rowL & 7) << 4);
        const uint32_t colA0 = (uint32_t)((lane >> 4) * 16);
        const int nl = ((lane >> 4) << 3) + (lane & 7);
        const uint32_t xorB = (uint32_t)((nl & 7) << 4);
        const uint32_t colB0 = (uint32_t)(((lane >> 3) & 1) * 16);

#pragma unroll
        for (int s16 = 0; s16 < 4; ++s16) {
#pragma unroll
            for (int mth = 0; mth < 2; ++mth) {
                uint32_t af[2][4];
#pragma unroll
                for (int q = 0; q < 2; ++q) {
                    const int mt = mth * 2 + q;
                    const uint32_t off = (uint32_t)(warpM + mt * 16 + rowL) * 128 +
                                         ((colA0 + s16 * 32) ^ xorA);
                    ldsm4(af[q][0], af[q][1], af[q][2], af[q][3], aB + off);
                }
#pragma unroll
                for (int np = 0; np < NT / 2; ++np) {
                    const uint32_t offB = (uint32_t)(warpN + np * 16 + nl) * 128 +
                                          ((colB0 + s16 * 32) ^ xorB);
                    uint32_t b0, b1, b2, b3;
                    ldsm4(b0, b1, b2, b3, bB + offB);
#pragma unroll
                    for (int q = 0; q < 2; ++q)
                        mma16816(acc[mth * 2 + q][2 * np], af[q], b0, b1);
#pragma unroll
                    for (int q = 0; q < 2; ++q)
                        mma16816(acc[mth * 2 + q][2 * np + 1], af[q], b2, b3);
                }
            }
        }
        __syncthreads();
    }

    // ---- epilogue: write C + per-column stats ----
    const int g = lane >> 2, tig = lane & 3;
#pragma unroll
    for (int mt = 0; mt < 4; ++mt) {
#pragma unroll
        for (int nt = 0; nt < NT; ++nt) {
            const int row = row0 + warpM + mt * 16 + g;
            const int col = warpN + nt * 8 + tig * 2;
            *(float2*)(C + (size_t)row * NOUT + col) =
                make_float2(acc[mt][nt][0], acc[mt][nt][1]);
            *(float2*)(C + (size_t)(row + 8) * NOUT + col) =
                make_float2(acc[mt][nt][2], acc[mt][nt][3]);
        }
    }
#pragma unroll
    for (int nt = 0; nt < NT; ++nt) {
        float s0 = 0.f, s1 = 0.f, q0 = 0.f, q1 = 0.f;
#pragma unroll
        for (int mt = 0; mt < 4; ++mt) {
            const float a0 = acc[mt][nt][0], a1 = acc[mt][nt][1];
            const float a2 = acc[mt][nt][2], a3 = acc[mt][nt][3];
            s0 += a0 + a2;  s1 += a1 + a3;
            q0 += a0 * a0 + a2 * a2;
            q1 += a1 * a1 + a3 * a3;
        }
#pragma unroll
        for (int o = 4; o < 32; o <<= 1) {
            s0 += __shfl_xor_sync(~0u, s0, o);
            s1 += __shfl_xor_sync(~0u, s1, o);
            q0 += __shfl_xor_sync(~0u, q0, o);
            q1 += __shfl_xor_sync(~0u, q1, o);
        }
        if (g == 0) {
            const int col = warpN + nt * 8 + tig * 2;
            atomicAdd(&sS[col], s0);  atomicAdd(&sS[col + 1], s1);
            atomicAdd(&sQ[col], q0);  atomicAdd(&sQ[col + 1], q1);
        }
    }
    __syncthreads();
    if (t < NOUT) {
        atomicAdd(statS + b * NOUT + t, sS[t]);
        atomicAdd(statQ + b * NOUT + t, sQ[t]);
        __threadfence();
    }
    __syncthreads();

    __shared__ int sLast;
    if (t == 0) sLast = (atomicAdd(&counter[b], 1) == 63);
    __syncthreads();
    if (sLast && t < NOUT) {
        const float s = *(volatile float*)(statS + b * NOUT + t);
        const float q = *(volatile float*)(statQ + b * NOUT + t);
        float gs = s, gq = q;
#pragma unroll
        for (int o = CPG >> 1; o; o >>= 1) {
            gs += __shfl_xor_sync(~0u, gs, o);
            gq += __shfl_xor_sync(~0u, gq, o);
        }
        const float cnt = (float)N1 * (float)CPG;
        const float mean = gs / cnt;
        const float var  = gq / cnt - mean * mean;
        const float rstd = rsqrtf(var + 1e-5f);
        const float sc = rstd * gw[t];
        oScale[b * NOUT + t] = sc;
        oShift[b * NOUT + t] = gb[t] - mean * sc;
    }
}

// ---------------- knn + interpolate + concat; extra blocks do weight prep ---
__device__ __forceinline__ void pack8_h(const float* x, __half* p)
{
    uint32_t w[4];
#pragma unroll
    for (int q = 0; q < 4; ++q)
        w[q] = h2bits(__floats2half2_rn(x[2 * q], x[2 * q + 1]));
    *(uint4*)p = make_uint4(w[0], w[1], w[2], w[3]);
}

__global__ __launch_bounds__(256) void knn_interp_kernel(
    const float* __restrict__ xyz1, const float* __restrict__ xyz2,
    const float* __restrict__ points1, const float* __restrict__ points2,
    const float* __restrict__ w0src, const float* __restrict__ w1src)
{
    const int b = blockIdx.y;

    if (blockIdx.x == N1 / 256) {   // prep slice: weights + zero accums
        const int t = threadIdx.x;
        for (int i = b * (H0 * CIN / BB) + t; i < (b + 1) * (H0 * CIN / BB); i += 256)
            g_w0h[i] = __float2half_rn(w0src[i]);
        for (int i = b * (H1 * H0 / BB) + t; i < (b + 1) * (H1 * H0 / BB); i += 256)
            g_w1h[i] = __float2half_rn(w1src[i]);
        if (b == 0) {
            for (int i = t; i < BB * H0; i += 256) { g_s0[i] = 0.f; g_q0[i] = 0.f; }
            for (int i = t; i < BB * H1; i += 256) { g_s1[i] = 0.f; g_q1[i] = 0.f; }
            if (t < BB) { g_cnt0[t] = 0; g_cnt1[t] = 0; }
        }
        return;
    }

    __shared__ float4 sp[M2];
    const float* x2 = xyz2 + (size_t)b * M2 * 3;
    for (int j = threadIdx.x; j < M2; j += 256) {
        float x = x2[j * 3 + 0], y = x2[j * 3 + 1], z = x2[j * 3 + 2];
        sp[j] = make_float4(x, y, z, x * x + y * y + z * z);
    }
    __syncthreads();

    const int n = blockIdx.x * 256 + threadIdx.x;
    const float* p1 = xyz1 + ((size_t)b * N1 + n) * 3;
    const float px = p1[0], py = p1[1], pz = p1[2];
    const float psq = px * px + py * py + pz * pz;

    float d0 = 1e30f, d1 = 1e30f, d2 = 1e30f;
    int i0 = 0, i1 = 0, i2 = 0;
#pragma unroll 4
    for (int j = 0; j < M2; ++j) {
        float4 q = sp[j];
        float tdot = fmaf(px, q.x, fmaf(py, q.y, pz * q.z));
        float d = psq + q.w - 2.0f * tdot;
        if (d < d2) {
            if (d < d1) {
                if (d < d0) { d2 = d1; i2 = i1; d1 = d0; i1 = i0; d0 = d; i0 = j; }
                else        { d2 = d1; i2 = i1; d1 = d;  i1 = j; }
            } else          { d2 = d;  i2 = j; }
        }
    }
    float w0 = 1.0f / (d0 + 1e-8f);
    float w1 = 1.0f / (d1 + 1e-8f);
    float w2 = 1.0f / (d2 + 1e-8f);
    const float inv = 1.0f / (w0 + w1 + w2);
    w0 *= inv; w1 *= inv; w2 *= inv;

    const size_t m = (size_t)b * N1 + n;
    __half* fh = g_fh + m * CIN;
    const float* pp1 = points1 + m * C1;

    float buf[8];
#pragma unroll 4
    for (int c = 0; c < C1; c += 8) {
        const float4 u = *(const float4*)(pp1 + c);
        const float4 v = *(const float4*)(pp1 + c + 4);
        buf[0] = u.x; buf[1] = u.y; buf[2] = u.z; buf[3] = u.w;
        buf[4] = v.x; buf[5] = v.y; buf[6] = v.z; buf[7] = v.w;
        pack8_h(buf, fh + c);
    }

    const float* r0 = points2 + ((size_t)b * M2 + i0) * C2;
    const float* r1 = points2 + ((size_t)b * M2 + i1) * C2;
    const float* r2 = points2 + ((size_t)b * M2 + i2) * C2;
#pragma unroll 4
    for (int c = 0; c < C2; c += 8) {
#pragma unroll
        for (int h = 0; h < 2; ++h) {
            const float4 a = *(const float4*)(r0 + c + h * 4);
            const float4 bb = *(const float4*)(r1 + c + h * 4);
            const float4 cc = *(const float4*)(r2 + c + h * 4);
            buf[h * 4 + 0] = w0 * a.x + w1 * bb.x + w2 * cc.x;
            buf[h * 4 + 1] = w0 * a.y + w1 * bb.y + w2 * cc.y;
            buf[h * 4 + 2] = w0 * a.z + w1 * bb.z + w2 * cc.z;
            buf[h * 4 + 3] = w0 * a.w + w1 * bb.w + w2 * cc.w;
        }
        pack8_h(buf, fh + C1 + c);
    }
}

// ---------------- final GN1 + ReLU in-place on d_out ------------------------
// Block handles 32 consecutive rows (within one batch). Lane owns 4 fixed
// channels -> scale/shift loaded ONCE per thread.
__global__ __launch_bounds__(256) void apply_kernel(
    float* __restrict__ out,
    const float* __restrict__ scale, const float* __restrict__ shift)
{
    const int lane = threadIdx.x & 31, w = threadIdx.x >> 5;
    const int row0 = blockIdx.x * 32;
    const int b = row0 >> 13;
    const int col = lane * 4;
    const float4 sc = *(const float4*)(scale + b * H1 + col);
    const float4 sh = *(const float4*)(shift + b * H1 + col);
#pragma unroll
    for (int i = 0; i < 4; ++i) {
        float* p = out + (size_t)(row0 + w * 4 + i) * H1 + col;
        float4 v = *(float4*)p;
        v.x = fmaxf(0.f, fmaf(v.x, sc.x, sh.x));
        v.y = fmaxf(0.f, fmaf(v.y, sc.y, sh.y));
        v.z = fmaxf(0.f, fmaf(v.z, sc.z, sh.z));
        v.w = fmaxf(0.f, fmaf(v.w, sc.w, sh.w));
        *(float4*)p = v;
    }
}

// ---------------- launcher ---------------------------------------------------
extern "C" void kernel_launch(void* const* d_in, const int* in_sizes, int n_in,
                              void* d_out, int out_size)
{
    const float* xyz1    = (const float*)d_in[0];
    const float* xyz2    = (const float*)d_in[1];
    const float* points1 = (const float*)d_in[2];
    const float* points2 = (const float*)d_in[3];
    const float* w0      = (const float*)d_in[4];
    const float* w1      = (const float*)d_in[5];
    const float* gn0w    = (const float*)d_in[6];
    const float* gn0b    = (const float*)d_in[7];
    const float* gn1w    = (const float*)d_in[8];
    const float* gn1b    = (const float*)d_in[9];
    float* out = (float*)d_out;

    __half *fh, *w0h, *w1h;
    float *h1, *sc0, *sh0, *sc1, *sh1, *s0, *q0, *s1, *q1;
    int *c0, *c1;
    cudaGetSymbolAddress((void**)&fh,  g_fh);
    cudaGetSymbolAddress((void**)&w0h, g_w0h);
    cudaGetSymbolAddress((void**)&w1h, g_w1h);
    cudaGetSymbolAddress((void**)&h1,  g_h1);
    cudaGetSymbolAddress((void**)&sc0, g_scale0);
    cudaGetSymbolAddress((void**)&sh0, g_shift0);
    cudaGetSymbolAddress((void**)&sc1, g_scale1);
    cudaGetSymbolAddress((void**)&sh1, g_shift1);
    cudaGetSymbolAddress((void**)&s0,  g_s0);
    cudaGetSymbolAddress((void**)&q0,  g_q0);
    cudaGetSymbolAddress((void**)&s1,  g_s1);
    cudaGetSymbolAddress((void**)&q1,  g_q1);
    cudaGetSymbolAddress((void**)&c0,  g_cnt0);
    cudaGetSymbolAddress((void**)&c1,  g_cnt1);

    const int SMEM1 = 2 * (16384 + H0 * 128) + 2 * H0 * 4;  // 100352
    const int SMEM2 = 2 * (16384 + H1 * 128) + 2 * H1 * 4;  // 66560
    cudaFuncSetAttribute(mma_gemm<CIN, H0, 0>,
                         cudaFuncAttributeMaxDynamicSharedMemorySize, SMEM1);
    cudaFuncSetAttribute(mma_gemm<H0, H1, 1>,
                         cudaFuncAttributeMaxDynamicSharedMemorySize, SMEM2);

    // 1) knn interp + concat (fp16 plane); last x-column does weight prep
    knn_interp_kernel<<<dim3(N1 / 256 + 1, BB), 256>>>(
        xyz1, xyz2, points1, points2, w0, w1);

    // 2) h1 = feat @ w0^T (fp16, 1 MMA/k16); fused GN0 stats + scale fold
    mma_gemm<CIN, H0, 0><<<NPTS / 128, 512, SMEM1>>>(
        fh, nullptr, w0h, h1, nullptr, nullptr,
        s0, q0, gn0w, gn0b, sc0, sh0, c0);

    // 3) out = relu(gn0(h1)) @ w1^T (fp16, 1 MMA/k16); fused GN1 stats
    mma_gemm<H0, H1, 1><<<NPTS / 128, 512, SMEM2>>>(
        nullptr, h1, w1h, out, sc0, sh0,
        s1, q1, gn1w, gn1b, sc1, sh1, c1);

    // 4) GN1 + ReLU in-place (fixed-channel mapping)
    apply_kernel<<<NPTS / 32, 256>>>(out, sc1, sh1);
}

// round 8
// speedup vs baseline: 3.0126x; 1.0180x over previous
#include <cuda_runtime.h>
#include <cuda_fp16.h>
#include <cstdint>
#include <cstddef>

// Problem constants (fixed by setup_inputs)
#define BB    8
#define N1    8192
#define M2    2048
#define C1    128
#define C2    256
#define CIN   384
#define H0    256
#define H1    128
#define NPTS  (BB * N1)   // 65536

// ---------------- scratch (device globals; no allocations allowed) ----------
__device__ __align__(16) __half g_fh[(size_t)NPTS * CIN];   // feat fp16
__device__ __align__(16) __half g_w0h[H0 * CIN];            // w0 fp16
__device__ __align__(16) __half g_w1h[H1 * H0];             // w1 fp16
__device__ __align__(16) __half g_h1[(size_t)NPTS * H0];    // h1 fp16 (33.5 MB)
__device__ float g_scale0[BB * H0];
__device__ float g_shift0[BB * H0];
__device__ float g_scale1[BB * H1];
__device__ float g_shift1[BB * H1];
__device__ float g_s0[BB * H0];
__device__ float g_q0[BB * H0];
__device__ float g_s1[BB * H1];
__device__ float g_q1[BB * H1];
__device__ int   g_cnt0[BB];
__device__ int   g_cnt1[BB];

// ---------------- PTX helpers ------------------------------------------------
__device__ __forceinline__ uint32_t smem_u32(const void* p) {
    uint32_t a;
    asm("{ .reg .u64 t; cvta.to.shared.u64 t, %1; cvt.u32.u64 %0, t; }"
        : "=r"(a) : "l"(p));
    return a;
}
__device__ __forceinline__ void cpa16(uint32_t dst, const void* src) {
    asm volatile("cp.async.cg.shared.global [%0], [%1], 16;"
                 :: "r"(dst), "l"(src) : "memory");
}
#define CP_COMMIT() asm volatile("cp.async.commit_group;" ::: "memory")
#define CP_WAIT(n)  asm volatile("cp.async.wait_group %0;" :: "n"(n) : "memory")

__device__ __forceinline__ void ldsm4(uint32_t& r0, uint32_t& r1,
                                      uint32_t& r2, uint32_t& r3, uint32_t a) {
    asm volatile("ldmatrix.sync.aligned.m8n8.x4.shared.b16 {%0,%1,%2,%3}, [%4];"
                 : "=r"(r0), "=r"(r1), "=r"(r2), "=r"(r3) : "r"(a));
}
__device__ __forceinline__ void mma16816(float* c, const uint32_t* a,
                                         uint32_t b0, uint32_t b1) {
    asm volatile(
        "mma.sync.aligned.m16n8k16.row.col.f32.f16.f16.f32 "
        "{%0,%1,%2,%3}, {%4,%5,%6,%7}, {%8,%9}, {%0,%1,%2,%3};"
        : "+f"(c[0]), "+f"(c[1]), "+f"(c[2]), "+f"(c[3])
        : "r"(a[0]), "r"(a[1]), "r"(a[2]), "r"(a[3]), "r"(b0), "r"(b1));
}
__device__ __forceinline__ uint32_t h2bits(__half2 v) {
    return *reinterpret_cast<uint32_t*>(&v);
}

// ---------------- fp16 GEMM on mma.sync + fused GN stats + fused scale ------
// C[m,n] = sum_k A'[m,k] * W[n,k]; block tile 128 x NOUT, 512 threads.
// MODE 0: A fp16 via cp.async; C written fp16.
// MODE 1: A fp16 + GN fold (smem-cached scale/shift) + relu at load; C fp32.
template <int K, int NOUT, int MODE>
__global__ __launch_bounds__(512, 1) void mma_gemm(
    const __half* __restrict__ Ah, const __half* __restrict__ Af,
    const __half* __restrict__ Bh,
    void* __restrict__ Cv,
    const float* __restrict__ scale, const float* __restrict__ shift,
    float* __restrict__ statS, float* __restrict__ statQ,
    const float* __restrict__ gw, const float* __restrict__ gb,
    float* __restrict__ oScale, float* __restrict__ oShift,
    int* __restrict__ counter)
{
    constexpr int CH = K / 64;
    constexpr int WN = NOUT / 8;          // columns per warp
    constexpr int NT = WN / 8;            // n8-tiles per warp
    constexpr int APLANE = 16384;         // 128 rows x 128B
    constexpr int BPLANE = NOUT * 128;
    constexpr int STAGE = APLANE + BPLANE;
    constexpr int BITER = NOUT / 64;
    constexpr int CPG = NOUT / 32;

    extern __shared__ __align__(128) char smem[];
    const uint32_t sb = smem_u32(smem);
    float* sS = (float*)(smem + 2 * STAGE);
    float* sQ = sS + NOUT;
    float* sScale = sQ + NOUT;            // [K] (MODE 1)
    float* sShift = sScale + K;
    const int t = threadIdx.x;
    const int wid = t >> 5, lane = t & 31;
    const int warpM = (wid >> 3) * 64;
    const int warpN = (wid & 7) * WN;
    const int row0 = blockIdx.x * 128;
    const int b = row0 >> 13;

    if (t < NOUT) { sS[t] = 0.f; sQ[t] = 0.f; }
    if (MODE == 1) {
        if (t < K) { sScale[t] = scale[b * K + t]; sShift[t] = shift[b * K + t]; }
        __syncthreads();
    }

    float acc[4][NT][4];
#pragma unroll
    for (int i = 0; i < 4; ++i)
#pragma unroll
        for (int j = 0; j < NT; ++j)
#pragma unroll
            for (int q = 0; q < 4; ++q) acc[i][j][q] = 0.f;

    float va[2][8];   // MODE 1 staging

    auto issueB = [&](int c, int s) {
#pragma unroll
        for (int i = 0; i < BITER; ++i) {
            const int id = t + i * 512;
            const int n = id >> 3, a = id & 7;
            const uint32_t swo = (uint32_t)(a * 16) ^ (uint32_t)((n & 7) << 4);
            cpa16(sb + s * STAGE + APLANE + n * 128 + swo,
                  Bh + (size_t)n * K + c * 64 + a * 8);
        }
    };
    auto issueA = [&](int c, int s) {     // MODE 0
#pragma unroll
        for (int i = 0; i < 2; ++i) {
            const int id = t + i * 512;
            const int r = id >> 3, a = id & 7;
            const uint32_t swo = (uint32_t)(a * 16) ^ (uint32_t)((r & 7) << 4);
            cpa16(sb + s * STAGE + r * 128 + swo,
                  Ah + (size_t)(row0 + r) * K + c * 64 + a * 8);
        }
    };
    auto ldgA = [&](int c) {              // MODE 1: fp16 load + GN fold + relu
#pragma unroll
        for (int i = 0; i < 2; ++i) {
            const int id = t + i * 512;
            const int r = id >> 3, a = id & 7;
            const uint4 raw = *(const uint4*)(Af + (size_t)(row0 + r) * K + c * 64 + a * 8);
            const __half2* hp = (const __half2*)&raw;
            const float2 f0 = __half22float2(hp[0]);
            const float2 f1 = __half22float2(hp[1]);
            const float2 f2 = __half22float2(hp[2]);
            const float2 f3 = __half22float2(hp[3]);
            const int col = c * 64 + a * 8;
            const float4 s0 = *(const float4*)(sScale + col);
            const float4 s1 = *(const float4*)(sScale + col + 4);
            const float4 h0 = *(const float4*)(sShift + col);
            const float4 h1 = *(const float4*)(sShift + col + 4);
            va[i][0] = fmaxf(0.f, fmaf(f0.x, s0.x, h0.x));
            va[i][1] = fmaxf(0.f, fmaf(f0.y, s0.y, h0.y));
            va[i][2] = fmaxf(0.f, fmaf(f1.x, s0.z, h0.z));
            va[i][3] = fmaxf(0.f, fmaf(f1.y, s0.w, h0.w));
            va[i][4] = fmaxf(0.f, fmaf(f2.x, s1.x, h1.x));
            va[i][5] = fmaxf(0.f, fmaf(f2.y, s1.y, h1.y));
            va[i][6] = fmaxf(0.f, fmaf(f3.x, s1.z, h1.z));
            va[i][7] = fmaxf(0.f, fmaf(f3.y, s1.w, h1.w));
        }
    };
    auto stsA = [&](int s) {              // MODE 1: fp16 convert + store
#pragma unroll
        for (int i = 0; i < 2; ++i) {
            const int id = t + i * 512;
            const int r = id >> 3, a = id & 7;
            uint32_t hw[4];
#pragma unroll
            for (int q = 0; q < 4; ++q)
                hw[q] = h2bits(__floats2half2_rn(va[i][2 * q], va[i][2 * q + 1]));
            const uint32_t swo = (uint32_t)(a * 16) ^ (uint32_t)((r & 7) << 4);
            asm volatile("st.shared.v4.b32 [%0], {%1,%2,%3,%4};"
                         :: "r"(sb + s * STAGE + r * 128 + swo),
                            "r"(hw[0]), "r"(hw[1]), "r"(hw[2]), "r"(hw[3]) : "memory");
        }
    };

    if (MODE == 1) { ldgA(0); issueB(0, 0); CP_COMMIT(); }
    else           { issueA(0, 0); issueB(0, 0); CP_COMMIT(); }

    for (int c = 0; c < CH; ++c) {
        const int s = c & 1;
        if (MODE == 1) {
            stsA(s);
            if (c + 1 < CH) { issueB(c + 1, s ^ 1); CP_COMMIT(); CP_WAIT(1); }
            else            { CP_WAIT(0); }
            __syncthreads();
            if (c + 1 < CH) ldgA(c + 1);
        } else {
            if (c + 1 < CH) {
                issueA(c + 1, s ^ 1);
                issueB(c + 1, s ^ 1);
                CP_COMMIT();
                CP_WAIT(1);
            } else {
                CP_WAIT(0);
            }
            __syncthreads();
        }

        const uint32_t aB = sb + s * STAGE;
        const uint32_t bB = aB + APLANE;

        const int rowL = lane & 15;
        const uint32_t xorA = (uint32_t)((rowL & 7) << 4);
        const uint32_t colA0 = (uint32_t)((lane >> 4) * 16);
        const int nl = ((lane >> 4) << 3) + (lane & 7);
        const uint32_t xorB = (uint32_t)((nl & 7) << 4);
        const uint32_t colB0 = (uint32_t)(((lane >> 3) & 1) * 16);

#pragma unroll
        for (int s16 = 0; s16 < 4; ++s16) {
#pragma unroll
            for (int mth = 0; mth < 2; ++mth) {
                uint32_t af[2][4];
#pragma unroll
                for (int q = 0; q < 2; ++q) {
                    const int mt = mth * 2 + q;
                    const uint32_t off = (uint32_t)(warpM + mt * 16 + rowL) * 128 +
                                         ((colA0 + s16 * 32) ^ xorA);
                    ldsm4(af[q][0], af[q][1], af[q][2], af[q][3], aB + off);
                }
#pragma unroll
                for (int np = 0; np < NT / 2; ++np) {
                    const uint32_t offB = (uint32_t)(warpN + np * 16 + nl) * 128 +
                                          ((colB0 + s16 * 32) ^ xorB);
                    uint32_t b0, b1, b2, b3;
                    ldsm4(b0, b1, b2, b3, bB + offB);
#pragma unroll
                    for (int q = 0; q < 2; ++q)
                        mma16816(acc[mth * 2 + q][2 * np], af[q], b0, b1);
#pragma unroll
                    for (int q = 0; q < 2; ++q)
                        mma16816(acc[mth * 2 + q][2 * np + 1], af[q], b2, b3);
                }
            }
        }
        __syncthreads();
    }

    // ---- epilogue: write C + per-column stats ----
    const int g = lane >> 2, tig = lane & 3;
    if (MODE == 0) {
        __half* Ch = (__half*)Cv;
#pragma unroll
        for (int mt = 0; mt < 4; ++mt) {
#pragma unroll
            for (int nt = 0; nt < NT; ++nt) {
                const int row = row0 + warpM + mt * 16 + g;
                const int col = warpN + nt * 8 + tig * 2;
                *(uint32_t*)(Ch + (size_t)row * NOUT + col) =
                    h2bits(__floats2half2_rn(acc[mt][nt][0], acc[mt][nt][1]));
                *(uint32_t*)(Ch + (size_t)(row + 8) * NOUT + col) =
                    h2bits(__floats2half2_rn(acc[mt][nt][2], acc[mt][nt][3]));
            }
        }
    } else {
        float* Cf = (float*)Cv;
#pragma unroll
        for (int mt = 0; mt < 4; ++mt) {
#pragma unroll
            for (int nt = 0; nt < NT; ++nt) {
                const int row = row0 + warpM + mt * 16 + g;
                const int col = warpN + nt * 8 + tig * 2;
                *(float2*)(Cf + (size_t)row * NOUT + col) =
                    make_float2(acc[mt][nt][0], acc[mt][nt][1]);
                *(float2*)(Cf + (size_t)(row + 8) * NOUT + col) =
                    make_float2(acc[mt][nt][2], acc[mt][nt][3]);
            }
        }
    }
#pragma unroll
    for (int nt = 0; nt < NT; ++nt) {
        float s0 = 0.f, s1 = 0.f, q0 = 0.f, q1 = 0.f;
#pragma unroll
        for (int mt = 0; mt < 4; ++mt) {
            const float a0 = acc[mt][nt][0], a1 = acc[mt][nt][1];
            const float a2 = acc[mt][nt][2], a3 = acc[mt][nt][3];
            s0 += a0 + a2;  s1 += a1 + a3;
            q0 += a0 * a0 + a2 * a2;
            q1 += a1 * a1 + a3 * a3;
        }
#pragma unroll
        for (int o = 4; o < 32; o <<= 1) {
            s0 += __shfl_xor_sync(~0u, s0, o);
            s1 += __shfl_xor_sync(~0u, s1, o);
            q0 += __shfl_xor_sync(~0u, q0, o);
            q1 += __shfl_xor_sync(~0u, q1, o);
        }
        if (g == 0) {
            const int col = warpN + nt * 8 + tig * 2;
            atomicAdd(&sS[col], s0);  atomicAdd(&sS[col + 1], s1);
            atomicAdd(&sQ[col], q0);  atomicAdd(&sQ[col + 1], q1);
        }
    }
    __syncthreads();
    if (t < NOUT) {
        atomicAdd(statS + b * NOUT + t, sS[t]);
        atomicAdd(statQ + b * NOUT + t, sQ[t]);
        __threadfence();
    }
    __syncthreads();

    __shared__ int sLast;
    if (t == 0) sLast = (atomicAdd(&counter[b], 1) == 63);
    __syncthreads();
    if (sLast && t < NOUT) {
        const float s = *(volatile float*)(statS + b * NOUT + t);
        const float q = *(volatile float*)(statQ + b * NOUT + t);
        float gs = s, gq = q;
#pragma unroll
        for (int o = CPG >> 1; o; o >>= 1) {
            gs += __shfl_xor_sync(~0u, gs, o);
            gq += __shfl_xor_sync(~0u, gq, o);
        }
        const float cnt = (float)N1 * (float)CPG;
        const float mean = gs / cnt;
        const float var  = gq / cnt - mean * mean;
        const float rstd = rsqrtf(var + 1e-5f);
        const float sc = rstd * gw[t];
        oScale[b * NOUT + t] = sc;
        oShift[b * NOUT + t] = gb[t] - mean * sc;
    }
}

// ---------------- knn + interpolate + concat; extra blocks do weight prep ---
__device__ __forceinline__ void pack8_h(const float* x, __half* p)
{
    uint32_t w[4];
#pragma unroll
    for (int q = 0; q < 4; ++q)
        w[q] = h2bits(__floats2half2_rn(x[2 * q], x[2 * q + 1]));
    *(uint4*)p = make_uint4(w[0], w[1], w[2], w[3]);
}

__global__ __launch_bounds__(256) void knn_interp_kernel(
    const float* __restrict__ xyz1, const float* __restrict__ xyz2,
    const float* __restrict__ points1, const float* __restrict__ points2,
    const float* __restrict__ w0src, const float* __restrict__ w1src)
{
    const int b = blockIdx.y;

    if (blockIdx.x == N1 / 256) {   // prep slice: weights + zero accums
        const int t = threadIdx.x;
        for (int i = b * (H0 * CIN / BB) + t; i < (b + 1) * (H0 * CIN / BB); i += 256)
            g_w0h[i] = __float2half_rn(w0src[i]);
        for (int i = b * (H1 * H0 / BB) + t; i < (b + 1) * (H1 * H0 / BB); i += 256)
            g_w1h[i] = __float2half_rn(w1src[i]);
        if (b == 0) {
            for (int i = t; i < BB * H0; i += 256) { g_s0[i] = 0.f; g_q0[i] = 0.f; }
            for (int i = t; i < BB * H1; i += 256) { g_s1[i] = 0.f; g_q1[i] = 0.f; }
            if (t < BB) { g_cnt0[t] = 0; g_cnt1[t] = 0; }
        }
        return;
    }

    // smem candidate: (-2x, -2y, -2z, |q|^2) so d' = 3 chained FMAs.
    __shared__ float4 sp[M2];
    const float* x2 = xyz2 + (size_t)b * M2 * 3;
    for (int j = threadIdx.x; j < M2; j += 256) {
        float x = x2[j * 3 + 0], y = x2[j * 3 + 1], z = x2[j * 3 + 2];
        sp[j] = make_float4(-2.f * x, -2.f * y, -2.f * z, x * x + y * y + z * z);
    }
    __syncthreads();

    const int n = blockIdx.x * 256 + threadIdx.x;
    const float* p1 = xyz1 + ((size_t)b * N1 + n) * 3;
    const float px = p1[0], py = p1[1], pz = p1[2];
    const float psq = px * px + py * py + pz * pz;

    // scan for top-3 of d' = d - psq (rank-equivalent)
    float d0 = 1e30f, d1 = 1e30f, d2 = 1e30f;
    int i0 = 0, i1 = 0, i2 = 0;
    auto insert = [&](float d, int j) {
        if (d < d2) {
            if (d < d1) {
                if (d < d0) { d2 = d1; i2 = i1; d1 = d0; i1 = i0; d0 = d; i0 = j; }
                else        { d2 = d1; i2 = i1; d1 = d;  i1 = j; }
            } else          { d2 = d;  i2 = j; }
        }
    };
#pragma unroll 4
    for (int j = 0; j < M2; j += 2) {
        const float4 qa = sp[j];
        const float4 qb = sp[j + 1];
        const float da = fmaf(px, qa.x, fmaf(py, qa.y, fmaf(pz, qa.z, qa.w)));
        const float db = fmaf(px, qb.x, fmaf(py, qb.y, fmaf(pz, qb.z, qb.w)));
        if (fminf(da, db) < d2) { insert(da, j); insert(db, j + 1); }
    }

    float w0 = 1.0f / ((d0 + psq) + 1e-8f);
    float w1 = 1.0f / ((d1 + psq) + 1e-8f);
    float w2 = 1.0f / ((d2 + psq) + 1e-8f);
    const float inv = 1.0f / (w0 + w1 + w2);
    w0 *= inv; w1 *= inv; w2 *= inv;

    const size_t m = (size_t)b * N1 + n;
    __half* fh = g_fh + m * CIN;
    const float* pp1 = points1 + m * C1;

    float buf[8];
#pragma unroll 4
    for (int c = 0; c < C1; c += 8) {
        const float4 u = *(const float4*)(pp1 + c);
        const float4 v = *(const float4*)(pp1 + c + 4);
        buf[0] = u.x; buf[1] = u.y; buf[2] = u.z; buf[3] = u.w;
        buf[4] = v.x; buf[5] = v.y; buf[6] = v.z; buf[7] = v.w;
        pack8_h(buf, fh + c);
    }

    const float* r0 = points2 + ((size_t)b * M2 + i0) * C2;
    const float* r1 = points2 + ((size_t)b * M2 + i1) * C2;
    const float* r2 = points2 + ((size_t)b * M2 + i2) * C2;
#pragma unroll 4
    for (int c = 0; c < C2; c += 8) {
#pragma unroll
        for (int h = 0; h < 2; ++h) {
            const float4 a = *(const float4*)(r0 + c + h * 4);
            const float4 bb = *(const float4*)(r1 + c + h * 4);
            const float4 cc = *(const float4*)(r2 + c + h * 4);
            buf[h * 4 + 0] = w0 * a.x + w1 * bb.x + w2 * cc.x;
            buf[h * 4 + 1] = w0 * a.y + w1 * bb.y + w2 * cc.y;
            buf[h * 4 + 2] = w0 * a.z + w1 * bb.z + w2 * cc.z;
            buf[h * 4 + 3] = w0 * a.w + w1 * bb.w + w2 * cc.w;
        }
        pack8_h(buf, fh + C1 + c);
    }
}

// ---------------- final GN1 + ReLU in-place on d_out ------------------------
__global__ __launch_bounds__(256) void apply_kernel(
    float* __restrict__ out,
    const float* __restrict__ scale, const float* __restrict__ shift)
{
    const int lane = threadIdx.x & 31, w = threadIdx.x >> 5;
    const int row0 = blockIdx.x * 32;
    const int b = row0 >> 13;
    const int col = lane * 4;
    const float4 sc = *(const float4*)(scale + b * H1 + col);
    const float4 sh = *(const float4*)(shift + b * H1 + col);
#pragma unroll
    for (int i = 0; i < 4; ++i) {
        float* p = out + (size_t)(row0 + w * 4 + i) * H1 + col;
        float4 v = *(float4*)p;
        v.x = fmaxf(0.f, fmaf(v.x, sc.x, sh.x));
        v.y = fmaxf(0.f, fmaf(v.y, sc.y, sh.y));
        v.z = fmaxf(0.f, fmaf(v.z, sc.z, sh.z));
        v.w = fmaxf(0.f, fmaf(v.w, sc.w, sh.w));
        *(float4*)p = v;
    }
}

// ---------------- launcher ---------------------------------------------------
extern "C" void kernel_launch(void* const* d_in, const int* in_sizes, int n_in,
                              void* d_out, int out_size)
{
    const float* xyz1    = (const float*)d_in[0];
    const float* xyz2    = (const float*)d_in[1];
    const float* points1 = (const float*)d_in[2];
    const float* points2 = (const float*)d_in[3];
    const float* w0      = (const float*)d_in[4];
    const float* w1      = (const float*)d_in[5];
    const float* gn0w    = (const float*)d_in[6];
    const float* gn0b    = (const float*)d_in[7];
    const float* gn1w    = (const float*)d_in[8];
    const float* gn1b    = (const float*)d_in[9];
    float* out = (float*)d_out;

    __half *fh, *w0h, *w1h, *h1;
    float *sc0, *sh0, *sc1, *sh1, *s0, *q0, *s1, *q1;
    int *c0, *c1;
    cudaGetSymbolAddress((void**)&fh,  g_fh);
    cudaGetSymbolAddress((void**)&w0h, g_w0h);
    cudaGetSymbolAddress((void**)&w1h, g_w1h);
    cudaGetSymbolAddress((void**)&h1,  g_h1);
    cudaGetSymbolAddress((void**)&sc0, g_scale0);
    cudaGetSymbolAddress((void**)&sh0, g_shift0);
    cudaGetSymbolAddress((void**)&sc1, g_scale1);
    cudaGetSymbolAddress((void**)&sh1, g_shift1);
    cudaGetSymbolAddress((void**)&s0,  g_s0);
    cudaGetSymbolAddress((void**)&q0,  g_q0);
    cudaGetSymbolAddress((void**)&s1,  g_s1);
    cudaGetSymbolAddress((void**)&q1,  g_q1);
    cudaGetSymbolAddress((void**)&c0,  g_cnt0);
    cudaGetSymbolAddress((void**)&c1,  g_cnt1);

    // smem: 2 stages + stats (2*NOUT) + scale/shift cache (2*K, MODE1)
    const int SMEM1 = 2 * (16384 + H0 * 128) + 2 * H0 * 4 + 2 * CIN * 4;  // ~103.4KB
    const int SMEM2 = 2 * (16384 + H1 * 128) + 2 * H1 * 4 + 2 * H0 * 4;   // ~68.6KB
    cudaFuncSetAttribute(mma_gemm<CIN, H0, 0>,
                         cudaFuncAttributeMaxDynamicSharedMemorySize, SMEM1);
    cudaFuncSetAttribute(mma_gemm<H0, H1, 1>,
                         cudaFuncAttributeMaxDynamicSharedMemorySize, SMEM2);

    // 1) knn interp + concat (fp16 plane); last x-column does weight prep
    knn_interp_kernel<<<dim3(N1 / 256 + 1, BB), 256>>>(
        xyz1, xyz2, points1, points2, w0, w1);

    // 2) h1(fp16) = feat @ w0^T; fused GN0 stats + scale fold
    mma_gemm<CIN, H0, 0><<<NPTS / 128, 512, SMEM1>>>(
        fh, nullptr, w0h, h1, nullptr, nullptr,
        s0, q0, gn0w, gn0b, sc0, sh0, c0);

    // 3) out(fp32) = relu(gn0(h1)) @ w1^T; fused GN1 stats
    mma_gemm<H0, H1, 1><<<NPTS / 128, 512, SMEM2>>>(
        nullptr, h1, w1h, out, sc0, sh0,
        s1, q1, gn1w, gn1b, sc1, sh1, c1);

    // 4) GN1 + ReLU in-place (fixed-channel mapping)
    apply_kernel<<<NPTS / 32, 256>>>(out, sc1, sh1);
}

// round 9
// speedup vs baseline: 3.8110x; 1.2650x over previous
#include <cuda_runtime.h>
#include <cuda_fp16.h>
#include <cstdint>
#include <cstddef>

// Problem constants (fixed by setup_inputs)
#define BB    8
#define N1    8192
#define M2    2048
#define C1    128
#define C2    256
#define CIN   384
#define H0    256
#define H1    128
#define NPTS  (BB * N1)   // 65536

// ---------------- scratch (device globals; no allocations allowed) ----------
__device__ __align__(16) __half g_fh[(size_t)NPTS * CIN];   // feat fp16
__device__ __align__(16) __half g_w0h[H0 * CIN];            // w0 fp16
__device__ __align__(16) __half g_w1h[H1 * H0];             // w1 fp16
__device__ __align__(16) __half g_h1[(size_t)NPTS * H0];    // h1 fp16
__device__ float g_scale0[BB * H0];
__device__ float g_shift0[BB * H0];
__device__ float g_scale1[BB * H1];
__device__ float g_shift1[BB * H1];
__device__ float g_s0[BB * H0];
__device__ float g_q0[BB * H0];
__device__ float g_s1[BB * H1];
__device__ float g_q1[BB * H1];
__device__ int   g_cnt0[BB];
__device__ int   g_cnt1[BB];

// ---------------- PTX helpers ------------------------------------------------
__device__ __forceinline__ uint32_t smem_u32(const void* p) {
    uint32_t a;
    asm("{ .reg .u64 t; cvta.to.shared.u64 t, %1; cvt.u32.u64 %0, t; }"
        : "=r"(a) : "l"(p));
    return a;
}
__device__ __forceinline__ void cpa16(uint32_t dst, const void* src) {
    asm volatile("cp.async.cg.shared.global [%0], [%1], 16;"
                 :: "r"(dst), "l"(src) : "memory");
}
#define CP_COMMIT() asm volatile("cp.async.commit_group;" ::: "memory")
#define CP_WAIT(n)  asm volatile("cp.async.wait_group %0;" :: "n"(n) : "memory")

__device__ __forceinline__ void ldsm4(uint32_t& r0, uint32_t& r1,
                                      uint32_t& r2, uint32_t& r3, uint32_t a) {
    asm volatile("ldmatrix.sync.aligned.m8n8.x4.shared.b16 {%0,%1,%2,%3}, [%4];"
                 : "=r"(r0), "=r"(r1), "=r"(r2), "=r"(r3) : "r"(a));
}
__device__ __forceinline__ void mma16816(float* c, const uint32_t* a,
                                         uint32_t b0, uint32_t b1) {
    asm volatile(
        "mma.sync.aligned.m16n8k16.row.col.f32.f16.f16.f32 "
        "{%0,%1,%2,%3}, {%4,%5,%6,%7}, {%8,%9}, {%0,%1,%2,%3};"
        : "+f"(c[0]), "+f"(c[1]), "+f"(c[2]), "+f"(c[3])
        : "r"(a[0]), "r"(a[1]), "r"(a[2]), "r"(a[3]), "r"(b0), "r"(b1));
}
__device__ __forceinline__ uint32_t h2bits(__half2 v) {
    return *reinterpret_cast<uint32_t*>(&v);
}

// ---------------- fp16 GEMM on mma.sync + fused GN stats + fused scale ------
// C[m,n] = sum_k A'[m,k] * W[n,k]; block tile 128 x NOUT, 512 threads.
// MODE 0: A fp16 via cp.async; C written fp16.
// MODE 1: A fp16 + GN fold (smem-cached scale/shift) + relu at load; C fp32.
template <int K, int NOUT, int MODE>
__global__ __launch_bounds__(512, 1) void mma_gemm(
    const __half* __restrict__ Ah, const __half* __restrict__ Af,
    const __half* __restrict__ Bh,
    void* __restrict__ Cv,
    const float* __restrict__ scale, const float* __restrict__ shift,
    float* __restrict__ statS, float* __restrict__ statQ,
    const float* __restrict__ gw, const float* __restrict__ gb,
    float* __restrict__ oScale, float* __restrict__ oShift,
    int* __restrict__ counter)
{
    constexpr int CH = K / 64;
    constexpr int WN = NOUT / 8;
    constexpr int NT = WN / 8;
    constexpr int APLANE = 16384;
    constexpr int BPLANE = NOUT * 128;
    constexpr int STAGE = APLANE + BPLANE;
    constexpr int BITER = NOUT / 64;
    constexpr int CPG = NOUT / 32;

    extern __shared__ __align__(128) char smem[];
    const uint32_t sb = smem_u32(smem);
    float* sS = (float*)(smem + 2 * STAGE);
    float* sQ = sS + NOUT;
    float* sScale = sQ + NOUT;            // [K] (MODE 1)
    float* sShift = sScale + K;
    const int t = threadIdx.x;
    const int wid = t >> 5, lane = t & 31;
    const int warpM = (wid >> 3) * 64;
    const int warpN = (wid & 7) * WN;
    const int row0 = blockIdx.x * 128;
    const int b = row0 >> 13;

    if (t < NOUT) { sS[t] = 0.f; sQ[t] = 0.f; }
    if (MODE == 1) {
        if (t < K) { sScale[t] = scale[b * K + t]; sShift[t] = shift[b * K + t]; }
        __syncthreads();
    }

    float acc[4][NT][4];
#pragma unroll
    for (int i = 0; i < 4; ++i)
#pragma unroll
        for (int j = 0; j < NT; ++j)
#pragma unroll
            for (int q = 0; q < 4; ++q) acc[i][j][q] = 0.f;

    float va[2][8];

    auto issueB = [&](int c, int s) {
#pragma unroll
        for (int i = 0; i < BITER; ++i) {
            const int id = t + i * 512;
            const int n = id >> 3, a = id & 7;
            const uint32_t swo = (uint32_t)(a * 16) ^ (uint32_t)((n & 7) << 4);
            cpa16(sb + s * STAGE + APLANE + n * 128 + swo,
                  Bh + (size_t)n * K + c * 64 + a * 8);
        }
    };
    auto issueA = [&](int c, int s) {
#pragma unroll
        for (int i = 0; i < 2; ++i) {
            const int id = t + i * 512;
            const int r = id >> 3, a = id & 7;
            const uint32_t swo = (uint32_t)(a * 16) ^ (uint32_t)((r & 7) << 4);
            cpa16(sb + s * STAGE + r * 128 + swo,
                  Ah + (size_t)(row0 + r) * K + c * 64 + a * 8);
        }
    };
    auto ldgA = [&](int c) {
#pragma unroll
        for (int i = 0; i < 2; ++i) {
            const int id = t + i * 512;
            const int r = id >> 3, a = id & 7;
            const uint4 raw = *(const uint4*)(Af + (size_t)(row0 + r) * K + c * 64 + a * 8);
            const __half2* hp = (const __half2*)&raw;
            const float2 f0 = __half22float2(hp[0]);
            const float2 f1 = __half22float2(hp[1]);
            const float2 f2 = __half22float2(hp[2]);
            const float2 f3 = __half22float2(hp[3]);
            const int col = c * 64 + a * 8;
            const float4 s0 = *(const float4*)(sScale + col);
            const float4 s1 = *(const float4*)(sScale + col + 4);
            const float4 h0 = *(const float4*)(sShift + col);
            const float4 h1 = *(const float4*)(sShift + col + 4);
            va[i][0] = fmaxf(0.f, fmaf(f0.x, s0.x, h0.x));
            va[i][1] = fmaxf(0.f, fmaf(f0.y, s0.y, h0.y));
            va[i][2] = fmaxf(0.f, fmaf(f1.x, s0.z, h0.z));
            va[i][3] = fmaxf(0.f, fmaf(f1.y, s0.w, h0.w));
            va[i][4] = fmaxf(0.f, fmaf(f2.x, s1.x, h1.x));
            va[i][5] = fmaxf(0.f, fmaf(f2.y, s1.y, h1.y));
            va[i][6] = fmaxf(0.f, fmaf(f3.x, s1.z, h1.z));
            va[i][7] = fmaxf(0.f, fmaf(f3.y, s1.w, h1.w));
        }
    };
    auto stsA = [&](int s) {
#pragma unroll
        for (int i = 0; i < 2; ++i) {
            const int id = t + i * 512;
            const int r = id >> 3, a = id & 7;
            uint32_t hw[4];
#pragma unroll
            for (int q = 0; q < 4; ++q)
                hw[q] = h2bits(__floats2half2_rn(va[i][2 * q], va[i][2 * q + 1]));
            const uint32_t swo = (uint32_t)(a * 16) ^ (uint32_t)((r & 7) << 4);
            asm volatile("st.shared.v4.b32 [%0], {%1,%2,%3,%4};"
                         :: "r"(sb + s * STAGE + r * 128 + swo),
                            "r"(hw[0]), "r"(hw[1]), "r"(hw[2]), "r"(hw[3]) : "memory");
        }
    };

    if (MODE == 1) { ldgA(0); issueB(0, 0); CP_COMMIT(); }
    else           { issueA(0, 0); issueB(0, 0); CP_COMMIT(); }

    for (int c = 0; c < CH; ++c) {
        const int s = c & 1;
        if (MODE == 1) {
            stsA(s);
            if (c + 1 < CH) { issueB(c + 1, s ^ 1); CP_COMMIT(); CP_WAIT(1); }
            else            { CP_WAIT(0); }
            __syncthreads();
            if (c + 1 < CH) ldgA(c + 1);
        } else {
            if (c + 1 < CH) {
                issueA(c + 1, s ^ 1);
                issueB(c + 1, s ^ 1);
                CP_COMMIT();
                CP_WAIT(1);
            } else {
                CP_WAIT(0);
            }
            __syncthreads();
        }

        const uint32_t aB = sb + s * STAGE;
        const uint32_t bB = aB + APLANE;

        const int rowL = lane & 15;
        const uint32_t xorA = (uint32_t)((rowL & 7) << 4);
        const uint32_t colA0 = (uint32_t)((lane >> 4) * 16);
        const int nl = ((lane >> 4) << 3) + (lane & 7);
        const uint32_t xorB = (uint32_t)((nl & 7) << 4);
        const uint32_t colB0 = (uint32_t)(((lane >> 3) & 1) * 16);

#pragma unroll
        for (int s16 = 0; s16 < 4; ++s16) {
#pragma unroll
            for (int mth = 0; mth < 2; ++mth) {
                uint32_t af[2][4];
#pragma unroll
                for (int q = 0; q < 2; ++q) {
                    const int mt = mth * 2 + q;
                    const uint32_t off = (uint32_t)(warpM + mt * 16 + rowL) * 128 +
                                         ((colA0 + s16 * 32) ^ xorA);
                    ldsm4(af[q][0], af[q][1], af[q][2], af[q][3], aB + off);
                }
#pragma unroll
                for (int np = 0; np < NT / 2; ++np) {
                    const uint32_t offB = (uint32_t)(warpN + np * 16 + nl) * 128 +
                                          ((colB0 + s16 * 32) ^ xorB);
                    uint32_t b0, b1, b2, b3;
                    ldsm4(b0, b1, b2, b3, bB + offB);
#pragma unroll
                    for (int q = 0; q < 2; ++q)
                        mma16816(acc[mth * 2 + q][2 * np], af[q], b0, b1);
#pragma unroll
                    for (int q = 0; q < 2; ++q)
                        mma16816(acc[mth * 2 + q][2 * np + 1], af[q], b2, b3);
                }
            }
        }
        __syncthreads();
    }

    // ---- epilogue: write C + per-column stats ----
    const int g = lane >> 2, tig = lane & 3;
    if (MODE == 0) {
        __half* Ch = (__half*)Cv;
#pragma unroll
        for (int mt = 0; mt < 4; ++mt) {
#pragma unroll
            for (int nt = 0; nt < NT; ++nt) {
                const int row = row0 + warpM + mt * 16 + g;
                const int col = warpN + nt * 8 + tig * 2;
                *(uint32_t*)(Ch + (size_t)row * NOUT + col) =
                    h2bits(__floats2half2_rn(acc[mt][nt][0], acc[mt][nt][1]));
                *(uint32_t*)(Ch + (size_t)(row + 8) * NOUT + col) =
                    h2bits(__floats2half2_rn(acc[mt][nt][2], acc[mt][nt][3]));
            }
        }
    } else {
        float* Cf = (float*)Cv;
#pragma unroll
        for (int mt = 0; mt < 4; ++mt) {
#pragma unroll
            for (int nt = 0; nt < NT; ++nt) {
                const int row = row0 + warpM + mt * 16 + g;
                const int col = warpN + nt * 8 + tig * 2;
                *(float2*)(Cf + (size_t)row * NOUT + col) =
                    make_float2(acc[mt][nt][0], acc[mt][nt][1]);
                *(float2*)(Cf + (size_t)(row + 8) * NOUT + col) =
                    make_float2(acc[mt][nt][2], acc[mt][nt][3]);
            }
        }
    }
#pragma unroll
    for (int nt = 0; nt < NT; ++nt) {
        float s0 = 0.f, s1 = 0.f, q0 = 0.f, q1 = 0.f;
#pragma unroll
        for (int mt = 0; mt < 4; ++mt) {
            const float a0 = acc[mt][nt][0], a1 = acc[mt][nt][1];
            const float a2 = acc[mt][nt][2], a3 = acc[mt][nt][3];
            s0 += a0 + a2;  s1 += a1 + a3;
            q0 += a0 * a0 + a2 * a2;
            q1 += a1 * a1 + a3 * a3;
        }
#pragma unroll
        for (int o = 4; o < 32; o <<= 1) {
            s0 += __shfl_xor_sync(~0u, s0, o);
            s1 += __shfl_xor_sync(~0u, s1, o);
            q0 += __shfl_xor_sync(~0u, q0, o);
            q1 += __shfl_xor_sync(~0u, q1, o);
        }
        if (g == 0) {
            const int col = warpN + nt * 8 + tig * 2;
            atomicAdd(&sS[col], s0);  atomicAdd(&sS[col + 1], s1);
            atomicAdd(&sQ[col], q0);  atomicAdd(&sQ[col + 1], q1);
        }
    }
    __syncthreads();
    if (t < NOUT) {
        atomicAdd(statS + b * NOUT + t, sS[t]);
        atomicAdd(statQ + b * NOUT + t, sQ[t]);
        __threadfence();
    }
    __syncthreads();

    __shared__ int sLast;
    if (t == 0) sLast = (atomicAdd(&counter[b], 1) == 63);
    __syncthreads();
    if (sLast && t < NOUT) {
        const float s = *(volatile float*)(statS + b * NOUT + t);
        const float q = *(volatile float*)(statQ + b * NOUT + t);
        float gs = s, gq = q;
#pragma unroll
        for (int o = CPG >> 1; o; o >>= 1) {
            gs += __shfl_xor_sync(~0u, gs, o);
            gq += __shfl_xor_sync(~0u, gq, o);
        }
        const float cnt = (float)N1 * (float)CPG;
        const float mean = gs / cnt;
        const float var  = gq / cnt - mean * mean;
        const float rstd = rsqrtf(var + 1e-5f);
        const float sc = rstd * gw[t];
        oScale[b * NOUT + t] = sc;
        oShift[b * NOUT + t] = gb[t] - mean * sc;
    }
}

// ---------------- knn + interpolate (warp-cooperative gather) ---------------
__global__ __launch_bounds__(256) void knn_interp_kernel(
    const float* __restrict__ xyz1, const float* __restrict__ xyz2,
    const float* __restrict__ points1, const float* __restrict__ points2,
    const float* __restrict__ w0src, const float* __restrict__ w1src)
{
    const int b = blockIdx.y;

    if (blockIdx.x == N1 / 256) {   // prep slice: weights + zero accums
        const int t = threadIdx.x;
        for (int i = b * (H0 * CIN / BB) + t; i < (b + 1) * (H0 * CIN / BB); i += 256)
            g_w0h[i] = __float2half_rn(w0src[i]);
        for (int i = b * (H1 * H0 / BB) + t; i < (b + 1) * (H1 * H0 / BB); i += 256)
            g_w1h[i] = __float2half_rn(w1src[i]);
        if (b == 0) {
            for (int i = t; i < BB * H0; i += 256) { g_s0[i] = 0.f; g_q0[i] = 0.f; }
            for (int i = t; i < BB * H1; i += 256) { g_s1[i] = 0.f; g_q1[i] = 0.f; }
            if (t < BB) { g_cnt0[t] = 0; g_cnt1[t] = 0; }
        }
        return;
    }

    // smem candidate: (-2x, -2y, -2z, |q|^2) so d' = 3 chained FMAs.
    __shared__ float4 sp[M2];                        // 32 KB
    __shared__ float sW0[256], sW1[256], sW2[256];   // per-point results
    __shared__ int   sI0[256], sI1[256], sI2[256];
    const float* x2 = xyz2 + (size_t)b * M2 * 3;
    for (int j = threadIdx.x; j < M2; j += 256) {
        float x = x2[j * 3 + 0], y = x2[j * 3 + 1], z = x2[j * 3 + 2];
        sp[j] = make_float4(-2.f * x, -2.f * y, -2.f * z, x * x + y * y + z * z);
    }
    __syncthreads();

    // ---- phase 1: per-thread top-3 scan ----
    const int n = blockIdx.x * 256 + threadIdx.x;
    const float* p1 = xyz1 + ((size_t)b * N1 + n) * 3;
    const float px = p1[0], py = p1[1], pz = p1[2];
    const float psq = px * px + py * py + pz * pz;

    float d0 = 1e30f, d1 = 1e30f, d2 = 1e30f;
    int i0 = 0, i1 = 0, i2 = 0;
    auto insert = [&](float d, int j) {
        if (d < d2) {
            if (d < d1) {
                if (d < d0) { d2 = d1; i2 = i1; d1 = d0; i1 = i0; d0 = d; i0 = j; }
                else        { d2 = d1; i2 = i1; d1 = d;  i1 = j; }
            } else          { d2 = d;  i2 = j; }
        }
    };
#pragma unroll 4
    for (int j = 0; j < M2; j += 2) {
        const float4 qa = sp[j];
        const float4 qb = sp[j + 1];
        const float da = fmaf(px, qa.x, fmaf(py, qa.y, fmaf(pz, qa.z, qa.w)));
        const float db = fmaf(px, qb.x, fmaf(py, qb.y, fmaf(pz, qb.z, qb.w)));
        if (fminf(da, db) < d2) { insert(da, j); insert(db, j + 1); }
    }

    {
        float w0 = 1.0f / ((d0 + psq) + 1e-8f);
        float w1 = 1.0f / ((d1 + psq) + 1e-8f);
        float w2 = 1.0f / ((d2 + psq) + 1e-8f);
        const float inv = 1.0f / (w0 + w1 + w2);
        sW0[threadIdx.x] = w0 * inv;
        sW1[threadIdx.x] = w1 * inv;
        sW2[threadIdx.x] = w2 * inv;
        sI0[threadIdx.x] = i0;
        sI1[threadIdx.x] = i1;
        sI2[threadIdx.x] = i2;
    }
    __syncthreads();

    // ---- phase 2: warp-cooperative gather + interpolate + concat ----
    const int lane = threadIdx.x & 31, w = threadIdx.x >> 5;
    const size_t mbase = (size_t)b * N1 + blockIdx.x * 256;
    const float* p2base = points2 + (size_t)b * M2 * C2;

#pragma unroll 2
    for (int pp = 0; pp < 32; ++pp) {
        const int p = w * 32 + pp;
        const size_t m = mbase + p;
        __half* fhp = g_fh + m * CIN;

        // points1 copy: lane owns 4 floats (fully coalesced)
        const float4 u = *(const float4*)(points1 + m * C1 + lane * 4);
        const uint32_t c01 = h2bits(__floats2half2_rn(u.x, u.y));
        const uint32_t c23 = h2bits(__floats2half2_rn(u.z, u.w));
        *(uint2*)(fhp + lane * 4) = make_uint2(c01, c23);

        // interpolation: lane owns 8 of 256 channels (fully coalesced rows)
        const float w0 = sW0[p], w1 = sW1[p], w2 = sW2[p];
        const float* r0 = p2base + (size_t)sI0[p] * C2 + lane * 8;
        const float* r1 = p2base + (size_t)sI1[p] * C2 + lane * 8;
        const float* r2 = p2base + (size_t)sI2[p] * C2 + lane * 8;
        uint32_t oh[4];
#pragma unroll
        for (int h = 0; h < 2; ++h) {
            const float4 a  = *(const float4*)(r0 + h * 4);
            const float4 bb = *(const float4*)(r1 + h * 4);
            const float4 cc = *(const float4*)(r2 + h * 4);
            const float o0 = w0 * a.x + w1 * bb.x + w2 * cc.x;
            const float o1 = w0 * a.y + w1 * bb.y + w2 * cc.y;
            const float o2 = w0 * a.z + w1 * bb.z + w2 * cc.z;
            const float o3 = w0 * a.w + w1 * bb.w + w2 * cc.w;
            oh[h * 2 + 0] = h2bits(__floats2half2_rn(o0, o1));
            oh[h * 2 + 1] = h2bits(__floats2half2_rn(o2, o3));
        }
        *(uint4*)(fhp + C1 + lane * 8) = make_uint4(oh[0], oh[1], oh[2], oh[3]);
    }
}

// ---------------- final GN1 + ReLU in-place on d_out ------------------------
__global__ __launch_bounds__(256) void apply_kernel(
    float* __restrict__ out,
    const float* __restrict__ scale, const float* __restrict__ shift)
{
    const int lane = threadIdx.x & 31, w = threadIdx.x >> 5;
    const int row0 = blockIdx.x * 32;
    const int b = row0 >> 13;
    const int col = lane * 4;
    const float4 sc = *(const float4*)(scale + b * H1 + col);
    const float4 sh = *(const float4*)(shift + b * H1 + col);
#pragma unroll
    for (int i = 0; i < 4; ++i) {
        float* p = out + (size_t)(row0 + w * 4 + i) * H1 + col;
        float4 v = *(float4*)p;
        v.x = fmaxf(0.f, fmaf(v.x, sc.x, sh.x));
        v.y = fmaxf(0.f, fmaf(v.y, sc.y, sh.y));
        v.z = fmaxf(0.f, fmaf(v.z, sc.z, sh.z));
        v.w = fmaxf(0.f, fmaf(v.w, sc.w, sh.w));
        *(float4*)p = v;
    }
}

// ---------------- launcher ---------------------------------------------------
extern "C" void kernel_launch(void* const* d_in, const int* in_sizes, int n_in,
                              void* d_out, int out_size)
{
    const float* xyz1    = (const float*)d_in[0];
    const float* xyz2    = (const float*)d_in[1];
    const float* points1 = (const float*)d_in[2];
    const float* points2 = (const float*)d_in[3];
    const float* w0      = (const float*)d_in[4];
    const float* w1      = (const float*)d_in[5];
    const float* gn0w    = (const float*)d_in[6];
    const float* gn0b    = (const float*)d_in[7];
    const float* gn1w    = (const float*)d_in[8];
    const float* gn1b    = (const float*)d_in[9];
    float* out = (float*)d_out;

    __half *fh, *w0h, *w1h, *h1;
    float *sc0, *sh0, *sc1, *sh1, *s0, *q0, *s1, *q1;
    int *c0, *c1;
    cudaGetSymbolAddress((void**)&fh,  g_fh);
    cudaGetSymbolAddress((void**)&w0h, g_w0h);
    cudaGetSymbolAddress((void**)&w1h, g_w1h);
    cudaGetSymbolAddress((void**)&h1,  g_h1);
    cudaGetSymbolAddress((void**)&sc0, g_scale0);
    cudaGetSymbolAddress((void**)&sh0, g_shift0);
    cudaGetSymbolAddress((void**)&sc1, g_scale1);
    cudaGetSymbolAddress((void**)&sh1, g_shift1);
    cudaGetSymbolAddress((void**)&s0,  g_s0);
    cudaGetSymbolAddress((void**)&q0,  g_q0);
    cudaGetSymbolAddress((void**)&s1,  g_s1);
    cudaGetSymbolAddress((void**)&q1,  g_q1);
    cudaGetSymbolAddress((void**)&c0,  g_cnt0);
    cudaGetSymbolAddress((void**)&c1,  g_cnt1);

    const int SMEM1 = 2 * (16384 + H0 * 128) + 2 * H0 * 4 + 2 * CIN * 4;
    const int SMEM2 = 2 * (16384 + H1 * 128) + 2 * H1 * 4 + 2 * H0 * 4;
    cudaFuncSetAttribute(mma_gemm<CIN, H0, 0>,
                         cudaFuncAttributeMaxDynamicSharedMemorySize, SMEM1);
    cudaFuncSetAttribute(mma_gemm<H0, H1, 1>,
                         cudaFuncAttributeMaxDynamicSharedMemorySize, SMEM2);

    // 1) knn interp + concat (warp-cooperative gather); last col: weight prep
    knn_interp_kernel<<<dim3(N1 / 256 + 1, BB), 256>>>(
        xyz1, xyz2, points1, points2, w0, w1);

    // 2) h1(fp16) = feat @ w0^T; fused GN0 stats + scale fold
    mma_gemm<CIN, H0, 0><<<NPTS / 128, 512, SMEM1>>>(
        fh, nullptr, w0h, h1, nullptr, nullptr,
        s0, q0, gn0w, gn0b, sc0, sh0, c0);

    // 3) out(fp32) = relu(gn0(h1)) @ w1^T; fused GN1 stats
    mma_gemm<H0, H1, 1><<<NPTS / 128, 512, SMEM2>>>(
        nullptr, h1, w1h, out, sc0, sh0,
        s1, q1, gn1w, gn1b, sc1, sh1, c1);

    // 4) GN1 + ReLU in-place (fixed-channel mapping)
    apply_kernel<<<NPTS / 32, 256>>>(out, sc1, sh1);
}